// round 6
// baseline (speedup 1.0000x reference)
#include <cuda_runtime.h>
#include <cuda_bf16.h>
#include <math.h>
#include <stdint.h>

// Problem constants
#define BB 4
#define NN 2048
#define VD 256
#define CD 64
#define HH 4
#define DD 64
#define INNER 256
#define ROWS (BB * NN)   // 8192

// ---------------- scratch (device globals; no allocation allowed) ----------
__device__ float g_Vn[ROWS * VD];          // LN(V)
__device__ float g_Cn[ROWS * CD];          // LN(C)
__device__ float g_qkv[ROWS * 2 * INNER];  // Vn @ W_vqk + b   (pre-rms)
__device__ float g_qkc[ROWS * 2 * INNER];  // Cn @ W_cqk + b   (pre-rms)
__device__ float g_ovp[ROWS * INNER];      // attn @ vv (pre out-proj)
__device__ float g_ocp[ROWS * INNER];      // attn @ vc (pre out-proj)

// pre-split bf16 hi/lo buffers, head-interleaved: [row][h*128 + d], d in 0..127
// d<64 = v-channel part, d>=64 = c-channel part. Q has qscale folded in.
__device__ __nv_bfloat16 g_Qh[ROWS * 512];
__device__ __nv_bfloat16 g_Ql[ROWS * 512];
__device__ __nv_bfloat16 g_Kh[ROWS * 512];
__device__ __nv_bfloat16 g_Kl[ROWS * 512];
__device__ __nv_bfloat16 g_Vh[ROWS * 512];
__device__ __nv_bfloat16 g_Vl[ROWS * 512];

// ---------------- LayerNorm -------------------------------------------------
template <int DIM>
__global__ void ln_kernel(const float* __restrict__ x, const float* __restrict__ g,
                          const float* __restrict__ b, float* __restrict__ out) {
    constexpr int NW = DIM / 32;
    __shared__ float red[NW];
    int row = blockIdx.x;
    int t = threadIdx.x;
    float v = x[row * DIM + t];

    float s = v;
    #pragma unroll
    for (int o = 16; o; o >>= 1) s += __shfl_xor_sync(0xFFFFFFFFu, s, o);
    if ((t & 31) == 0) red[t >> 5] = s;
    __syncthreads();
    float tot = 0.f;
    #pragma unroll
    for (int i = 0; i < NW; i++) tot += red[i];
    float mean = tot / (float)DIM;
    __syncthreads();

    float d = v - mean;
    float s2 = d * d;
    #pragma unroll
    for (int o = 16; o; o >>= 1) s2 += __shfl_xor_sync(0xFFFFFFFFu, s2, o);
    if ((t & 31) == 0) red[t >> 5] = s2;
    __syncthreads();
    float var = 0.f;
    #pragma unroll
    for (int i = 0; i < NW; i++) var += red[i];
    var /= (float)DIM;

    out[row * DIM + t] = d * rsqrtf(var + 1e-5f) * g[t] + b[t];
}

// ---- RMSNorm over 512 + split-bf16 write to head-interleaved Q/K buffers ---
// x row = [q(256) | k(256)]. Q gets qscale. coff = 0 (v-channel) or 64 (c-chan).
__global__ void rms512_split_kernel(const float* __restrict__ x, const float* __restrict__ s,
                                    __nv_bfloat16* __restrict__ Qh, __nv_bfloat16* __restrict__ Ql,
                                    __nv_bfloat16* __restrict__ Kh, __nv_bfloat16* __restrict__ Kl,
                                    int coff) {
    __shared__ float red[8];
    int row = blockIdx.x;
    int t = threadIdx.x;   // 256 threads, 2 elems each
    const float* xr = x + (size_t)row * 512;
    float a = xr[t], c = xr[t + 256];
    float ss = a * a + c * c;
    #pragma unroll
    for (int o = 16; o; o >>= 1) ss += __shfl_xor_sync(0xFFFFFFFFu, ss, o);
    if ((t & 31) == 0) red[t >> 5] = ss;
    __syncthreads();
    float tot = 0.f;
    #pragma unroll
    for (int i = 0; i < 8; i++) tot += red[i];
    float r = rsqrtf(tot / 512.f + 1e-6f);

    float qv = a * r * s[t] * 0.125f;          // qscale folded in
    float kv = c * r * s[t + 256];
    int h = t >> 6, d = t & 63;
    size_t di = (size_t)row * 512 + h * 128 + coff + d;
    float qh = __bfloat162float(__float2bfloat16_rn(qv));
    Qh[di] = __float2bfloat16_rn(qh);
    Ql[di] = __float2bfloat16_rn(qv - qh);
    float kh = __bfloat162float(__float2bfloat16_rn(kv));
    Kh[di] = __float2bfloat16_rn(kh);
    Kl[di] = __float2bfloat16_rn(kv - kh);
}

// ---------------- Tiled SGEMM + bias -----------------------------------------
// If bh != nullptr: instead of fp32 C, write split-bf16 to bh/bl with
// head-interleave dst col = (n>>6)*128 + coff + (n&63), row stride 512.
__global__ void gemm_bias_kernel(const float* __restrict__ A, const float* __restrict__ W,
                                 const float* __restrict__ bias, float* __restrict__ C,
                                 int M, int K, int Nc,
                                 __nv_bfloat16* __restrict__ bh,
                                 __nv_bfloat16* __restrict__ bl, int coff) {
    __shared__ float As[16][64];   // [k][m]
    __shared__ float Ws[16][64];   // [k][n]
    int bm0 = blockIdx.y * 64;
    int bn0 = blockIdx.x * 64;
    int tid = threadIdx.x;
    int tx = tid & 15, ty = tid >> 4;

    float acc[4][4] = {};

    int arow  = tid >> 2;
    int acol4 = (tid & 3) * 4;
    int wrow  = tid >> 4;
    int wcol4 = (tid & 15) * 4;

    for (int k0 = 0; k0 < K; k0 += 16) {
        float4 av = *(const float4*)&A[(size_t)(bm0 + arow) * K + k0 + acol4];
        As[acol4 + 0][arow] = av.x;
        As[acol4 + 1][arow] = av.y;
        As[acol4 + 2][arow] = av.z;
        As[acol4 + 3][arow] = av.w;
        float4 wv = *(const float4*)&W[(size_t)(k0 + wrow) * Nc + bn0 + wcol4];
        *(float4*)&Ws[wrow][wcol4] = wv;
        __syncthreads();
        #pragma unroll
        for (int k = 0; k < 16; k++) {
            float4 a = *(const float4*)&As[k][ty * 4];
            float4 w = *(const float4*)&Ws[k][tx * 4];
            acc[0][0] += a.x * w.x; acc[0][1] += a.x * w.y; acc[0][2] += a.x * w.z; acc[0][3] += a.x * w.w;
            acc[1][0] += a.y * w.x; acc[1][1] += a.y * w.y; acc[1][2] += a.y * w.z; acc[1][3] += a.y * w.w;
            acc[2][0] += a.z * w.x; acc[2][1] += a.z * w.y; acc[2][2] += a.z * w.z; acc[2][3] += a.z * w.w;
            acc[3][0] += a.w * w.x; acc[3][1] += a.w * w.y; acc[3][2] += a.w * w.z; acc[3][3] += a.w * w.w;
        }
        __syncthreads();
    }
    if (bh) {
        #pragma unroll
        for (int i = 0; i < 4; i++) {
            int m = bm0 + ty * 4 + i;
            #pragma unroll
            for (int j = 0; j < 4; j++) {
                int n = bn0 + tx * 4 + j;
                float v = acc[i][j] + bias[n];
                float vh = __bfloat162float(__float2bfloat16_rn(v));
                size_t di = (size_t)m * 512 + ((n >> 6) * 128 + coff + (n & 63));
                bh[di] = __float2bfloat16_rn(vh);
                bl[di] = __float2bfloat16_rn(v - vh);
            }
        }
    } else {
        #pragma unroll
        for (int i = 0; i < 4; i++) {
            int m = bm0 + ty * 4 + i;
            #pragma unroll
            for (int j = 0; j < 4; j++) {
                int n = bn0 + tx * 4 + j;
                C[(size_t)m * Nc + n] = acc[i][j] + bias[n];
            }
        }
    }
}

// ---------------- Tensor-core attention (split-bf16 x3, flash-style) -------
// d=128 (qv||qc), TQ=TK=64, 256 threads = 8 warps arranged 2(m) x 4(n).
// K/V share one 32-token chunk buffer -> smem 88.8KB -> 2 CTAs/SM.

#define LDSM_X4(r0,r1,r2,r3,addr) \
    asm volatile("ldmatrix.sync.aligned.m8n8.x4.shared.b16 {%0,%1,%2,%3}, [%4];" \
        : "=r"(r0),"=r"(r1),"=r"(r2),"=r"(r3) : "r"(addr))

#define LDSM_X4_T(r0,r1,r2,r3,addr) \
    asm volatile("ldmatrix.sync.aligned.m8n8.x4.trans.shared.b16 {%0,%1,%2,%3}, [%4];" \
        : "=r"(r0),"=r"(r1),"=r"(r2),"=r"(r3) : "r"(addr))

#define MMA_BF16(C, A, b0_, b1_) \
    asm volatile("mma.sync.aligned.m16n8k16.row.col.f32.bf16.bf16.f32 " \
        "{%0,%1,%2,%3}, {%4,%5,%6,%7}, {%8,%9}, {%0,%1,%2,%3};" \
        : "+f"((C)[0]), "+f"((C)[1]), "+f"((C)[2]), "+f"((C)[3]) \
        : "r"((A)[0]), "r"((A)[1]), "r"((A)[2]), "r"((A)[3]), "r"(b0_), "r"(b1_))

struct AttnSmem {
    __nv_bfloat16 Qh[64][136];   // 17408 B
    __nv_bfloat16 Ql[64][136];
    __nv_bfloat16 Bh[32][136];   // K or V chunk (32 tokens x 128 dims), 8704 B
    __nv_bfloat16 Bl[32][136];
    float Ss[64][68];            // 17408 B
    __nv_bfloat16 Ph[64][72];    // 9216 B
    __nv_bfloat16 Pl[64][72];
    float m_s[64];
    float l_s[64];
    float alpha_s[64];
};  // ~88.8 KB

static __device__ __forceinline__ uint32_t smem_u32(const void* p) {
    return (uint32_t)__cvta_generic_to_shared(p);
}

__global__ void __launch_bounds__(256, 2)
attn_kernel(const __nv_bfloat16* __restrict__ gQh, const __nv_bfloat16* __restrict__ gQl,
            const __nv_bfloat16* __restrict__ gKh, const __nv_bfloat16* __restrict__ gKl,
            const __nv_bfloat16* __restrict__ gVh, const __nv_bfloat16* __restrict__ gVl,
            float* __restrict__ ovp, float* __restrict__ ocp) {
    extern __shared__ char smraw[];
    AttnSmem& sm = *(AttnSmem*)smraw;
    int tid = threadIdx.x;
    int lane = tid & 31;
    int w = tid >> 5;
    int wm = w >> 2;          // 0..1
    int wn = w & 3;           // 0..3
    int m0 = wm * 32;
    int cw0 = wn * 32;        // O columns for this warp
    int g = lane >> 2, t4 = lane & 3;

    int bh_ = blockIdx.y;
    int b = bh_ >> 2;
    int h = bh_ & 3;
    int n0q = blockIdx.x * 64;

    const uint32_t QHL = 64 * 136 * 2;   // Qh -> Ql byte offset
    const uint32_t BHL = 32 * 136 * 2;   // Bh -> Bl
    const uint32_t PHL = 64 * 72 * 2;    // Ph -> Pl

    // ---- Fill Q tile (hi+lo), pure copy; qscale already folded in ----
    for (int idx = tid; idx < 1024; idx += 256) {
        int tok = idx >> 4;
        int c8 = (idx & 15) << 3;
        size_t base = (size_t)(b * NN + n0q + tok) * 512 + h * 128 + c8;
        *(uint4*)&sm.Qh[tok][c8] = *(const uint4*)&gQh[base];
        *(uint4*)&sm.Ql[tok][c8] = *(const uint4*)&gQl[base];
    }
    if (tid < 64) { sm.m_s[tid] = -1e30f; sm.l_s[tid] = 0.f; }

    float cO[2][4][4] = {};
    __syncthreads();

    for (int jt = 0; jt < NN / 64; jt++) {
        int kn0 = jt * 64;
        float cS[2][2][4] = {};   // [mt][chunk][frag]

        // ======== QK over two 32-token chunks ========
        #pragma unroll
        for (int ch = 0; ch < 2; ch++) {
            // fill K chunk (tokens kn0 + ch*32 .. +31)
            for (int idx = tid; idx < 512; idx += 256) {
                int tok = idx >> 4;
                int c8 = (idx & 15) << 3;
                size_t base = (size_t)(b * NN + kn0 + ch * 32 + tok) * 512 + h * 128 + c8;
                *(uint4*)&sm.Bh[tok][c8] = *(const uint4*)&gKh[base];
                *(uint4*)&sm.Bl[tok][c8] = *(const uint4*)&gKl[base];
            }
            __syncthreads();

            // S[:, ch*32 + wn*8 .. +7] += Q @ K^T
            #pragma unroll
            for (int kb = 0; kb < 4; kb++) {
                int k0 = kb * 32;
                uint32_t bhr[4], blr[4];
                uint32_t baddr = smem_u32(&sm.Bh[wn * 8 + (lane & 7)][k0 + (lane >> 3) * 8]);
                LDSM_X4(bhr[0], bhr[1], bhr[2], bhr[3], baddr);
                LDSM_X4(blr[0], blr[1], blr[2], blr[3], baddr + BHL);
                #pragma unroll
                for (int sub = 0; sub < 2; sub++) {
                    int kk0 = k0 + sub * 16;
                    #pragma unroll
                    for (int mt = 0; mt < 2; mt++) {
                        uint32_t ah[4], al[4];
                        uint32_t addr = smem_u32(&sm.Qh[m0 + mt * 16 + (lane & 15)][kk0 + (lane >> 4) * 8]);
                        LDSM_X4(ah[0], ah[1], ah[2], ah[3], addr);
                        LDSM_X4(al[0], al[1], al[2], al[3], addr + QHL);
                        MMA_BF16(cS[mt][ch], ah, bhr[sub * 2], bhr[sub * 2 + 1]);
                        MMA_BF16(cS[mt][ch], ah, blr[sub * 2], blr[sub * 2 + 1]);
                        MMA_BF16(cS[mt][ch], al, bhr[sub * 2], bhr[sub * 2 + 1]);
                    }
                }
            }
            __syncthreads();   // Bbuf reads done (safe to refill)
        }

        // write S to smem
        #pragma unroll
        for (int mt = 0; mt < 2; mt++) {
            #pragma unroll
            for (int ch = 0; ch < 2; ch++) {
                int r0 = m0 + mt * 16 + g;
                int c = ch * 32 + wn * 8 + t4 * 2;
                sm.Ss[r0][c]     = cS[mt][ch][0];
                sm.Ss[r0][c + 1] = cS[mt][ch][1];
                sm.Ss[r0 + 8][c]     = cS[mt][ch][2];
                sm.Ss[r0 + 8][c + 1] = cS[mt][ch][3];
            }
        }
        __syncthreads();

        // ---- Online softmax (rows w*8..w*8+7) + fill V chunk 0 ----
        #pragma unroll
        for (int rr = 0; rr < 8; rr++) {
            int r = w * 8 + rr;
            float x0 = sm.Ss[r][lane];
            float x1 = sm.Ss[r][lane + 32];
            float mx = fmaxf(x0, x1);
            #pragma unroll
            for (int o = 16; o; o >>= 1) mx = fmaxf(mx, __shfl_xor_sync(0xFFFFFFFFu, mx, o));
            float m_old = sm.m_s[r];
            float m_new = fmaxf(m_old, mx);
            float p0 = __expf(x0 - m_new);
            float p1 = __expf(x1 - m_new);
            float p0h = __bfloat162float(__float2bfloat16_rn(p0));
            float p1h = __bfloat162float(__float2bfloat16_rn(p1));
            sm.Ph[r][lane]      = __float2bfloat16_rn(p0h);
            sm.Ph[r][lane + 32] = __float2bfloat16_rn(p1h);
            sm.Pl[r][lane]      = __float2bfloat16_rn(p0 - p0h);
            sm.Pl[r][lane + 32] = __float2bfloat16_rn(p1 - p1h);
            float sum = p0 + p1;
            #pragma unroll
            for (int o = 16; o; o >>= 1) sum += __shfl_xor_sync(0xFFFFFFFFu, sum, o);
            if (lane == 0) {
                float alpha = __expf(m_old - m_new);
                sm.alpha_s[r] = alpha;
                sm.l_s[r] = sm.l_s[r] * alpha + sum;
                sm.m_s[r] = m_new;
            }
        }
        // fill V chunk 0 (Bbuf free since last sync)
        for (int idx = tid; idx < 512; idx += 256) {
            int tok = idx >> 4;
            int c8 = (idx & 15) << 3;
            size_t base = (size_t)(b * NN + kn0 + tok) * 512 + h * 128 + c8;
            *(uint4*)&sm.Bh[tok][c8] = *(const uint4*)&gVh[base];
            *(uint4*)&sm.Bl[tok][c8] = *(const uint4*)&gVl[base];
        }
        __syncthreads();

        // ---- Rescale O accumulators by alpha ----
        #pragma unroll
        for (int mt = 0; mt < 2; mt++) {
            float al0 = sm.alpha_s[m0 + mt * 16 + g];
            float al1 = sm.alpha_s[m0 + mt * 16 + 8 + g];
            #pragma unroll
            for (int nf = 0; nf < 4; nf++) {
                cO[mt][nf][0] *= al0; cO[mt][nf][1] *= al0;
                cO[mt][nf][2] *= al1; cO[mt][nf][3] *= al1;
            }
        }

        // ======== PV over two 32-token chunks ========
        #pragma unroll
        for (int ch = 0; ch < 2; ch++) {
            if (ch == 1) {
                __syncthreads();   // PV chunk0 reads done
                for (int idx = tid; idx < 512; idx += 256) {
                    int tok = idx >> 4;
                    int c8 = (idx & 15) << 3;
                    size_t base = (size_t)(b * NN + kn0 + 32 + tok) * 512 + h * 128 + c8;
                    *(uint4*)&sm.Bh[tok][c8] = *(const uint4*)&gVh[base];
                    *(uint4*)&sm.Bl[tok][c8] = *(const uint4*)&gVl[base];
                }
                __syncthreads();
            }
            #pragma unroll
            for (int kk = 0; kk < 2; kk++) {
                int k0 = kk * 16;    // local token base within chunk
                uint32_t ah[2][4], al[2][4];
                #pragma unroll
                for (int mt = 0; mt < 2; mt++) {
                    uint32_t addr = smem_u32(&sm.Ph[m0 + mt * 16 + (lane & 15)]
                                                   [ch * 32 + k0 + (lane >> 4) * 8]);
                    LDSM_X4(ah[mt][0], ah[mt][1], ah[mt][2], ah[mt][3], addr);
                    LDSM_X4(al[mt][0], al[mt][1], al[mt][2], al[mt][3], addr + PHL);
                }
                uint32_t bhv[2][4], blv[2][4];
                #pragma unroll
                for (int nh = 0; nh < 2; nh++) {
                    uint32_t addr = smem_u32(&sm.Bh[k0 + ((lane >> 3) & 1) * 8 + (lane & 7)]
                                                   [cw0 + nh * 16 + (lane >> 4) * 8]);
                    LDSM_X4_T(bhv[nh][0], bhv[nh][1], bhv[nh][2], bhv[nh][3], addr);
                    LDSM_X4_T(blv[nh][0], blv[nh][1], blv[nh][2], blv[nh][3], addr + BHL);
                }
                #pragma unroll
                for (int mt = 0; mt < 2; mt++) {
                    #pragma unroll
                    for (int nf = 0; nf < 4; nf++) {
                        int nh = nf >> 1, sub = nf & 1;
                        MMA_BF16(cO[mt][nf], ah[mt], bhv[nh][sub * 2], bhv[nh][sub * 2 + 1]);
                        MMA_BF16(cO[mt][nf], ah[mt], blv[nh][sub * 2], blv[nh][sub * 2 + 1]);
                        MMA_BF16(cO[mt][nf], al[mt], bhv[nh][sub * 2], bhv[nh][sub * 2 + 1]);
                    }
                }
            }
        }
        __syncthreads();   // Bbuf + P free for next tile
    }

    // ---- Epilogue: normalize, write ovp / ocp ----
    #pragma unroll
    for (int mt = 0; mt < 2; mt++) {
        float li0 = 1.f / sm.l_s[m0 + mt * 16 + g];
        float li1 = 1.f / sm.l_s[m0 + mt * 16 + 8 + g];
        size_t row0 = (size_t)(b * NN + n0q + m0 + mt * 16 + g);
        size_t row1 = row0 + 8;
        #pragma unroll
        for (int nf = 0; nf < 4; nf++) {
            int c = cw0 + nf * 8 + t4 * 2;
            float2 o0 = make_float2(cO[mt][nf][0] * li0, cO[mt][nf][1] * li0);
            float2 o1 = make_float2(cO[mt][nf][2] * li1, cO[mt][nf][3] * li1);
            if (c < 64) {
                *(float2*)&ovp[row0 * 256 + h * 64 + c] = o0;
                *(float2*)&ovp[row1 * 256 + h * 64 + c] = o1;
            } else {
                *(float2*)&ocp[row0 * 256 + h * 64 + (c - 64)] = o0;
                *(float2*)&ocp[row1 * 256 + h * 64 + (c - 64)] = o1;
            }
        }
    }
}

// ---------------- launch ----------------------------------------------------
extern "C" void kernel_launch(void* const* d_in, const int* in_sizes, int n_in,
                              void* d_out, int out_size) {
    const float* V     = (const float*)d_in[0];
    const float* C     = (const float*)d_in[1];
    const float* vn_g  = (const float*)d_in[2];
    const float* vn_b  = (const float*)d_in[3];
    const float* cn_g  = (const float*)d_in[4];
    const float* cn_b  = (const float*)d_in[5];
    const float* W_vqk = (const float*)d_in[6];
    const float* b_vqk = (const float*)d_in[7];
    const float* rms_v = (const float*)d_in[8];
    const float* W_cqk = (const float*)d_in[9];
    const float* b_cqk = (const float*)d_in[10];
    const float* rms_c = (const float*)d_in[11];
    const float* W_vv  = (const float*)d_in[12];
    const float* b_vv  = (const float*)d_in[13];
    const float* W_cv  = (const float*)d_in[14];
    const float* b_cv  = (const float*)d_in[15];
    const float* W_ov  = (const float*)d_in[16];
    const float* b_ov  = (const float*)d_in[17];
    const float* W_oc  = (const float*)d_in[18];
    const float* b_oc  = (const float*)d_in[19];

    float* out_v = (float*)d_out;                    // (B,N,VD)
    float* out_c = out_v + (size_t)ROWS * VD;        // (B,N,CD)

    float *pVn, *pCn, *pqkv, *pqkc, *povp, *pocp;
    __nv_bfloat16 *pQh, *pQl, *pKh, *pKl, *pVh, *pVl;
    cudaGetSymbolAddress((void**)&pVn,  g_Vn);
    cudaGetSymbolAddress((void**)&pCn,  g_Cn);
    cudaGetSymbolAddress((void**)&pqkv, g_qkv);
    cudaGetSymbolAddress((void**)&pqkc, g_qkc);
    cudaGetSymbolAddress((void**)&povp, g_ovp);
    cudaGetSymbolAddress((void**)&pocp, g_ocp);
    cudaGetSymbolAddress((void**)&pQh, g_Qh);
    cudaGetSymbolAddress((void**)&pQl, g_Ql);
    cudaGetSymbolAddress((void**)&pKh, g_Kh);
    cudaGetSymbolAddress((void**)&pKl, g_Kl);
    cudaGetSymbolAddress((void**)&pVh, g_Vh);
    cudaGetSymbolAddress((void**)&pVl, g_Vl);

    // 1. LayerNorms
    ln_kernel<VD><<<ROWS, VD>>>(V, vn_g, vn_b, pVn);
    ln_kernel<CD><<<ROWS, CD>>>(C, cn_g, cn_b, pCn);

    // 2. Projections (qk -> fp32 for rms; v -> split-bf16 directly)
    gemm_bias_kernel<<<dim3(512 / 64, ROWS / 64), 256>>>(pVn, W_vqk, b_vqk, pqkv, ROWS, VD, 512,
                                                         nullptr, nullptr, 0);
    gemm_bias_kernel<<<dim3(512 / 64, ROWS / 64), 256>>>(pCn, W_cqk, b_cqk, pqkc, ROWS, CD, 512,
                                                         nullptr, nullptr, 0);
    gemm_bias_kernel<<<dim3(256 / 64, ROWS / 64), 256>>>(pVn, W_vv,  b_vv,  nullptr, ROWS, VD, 256,
                                                         pVh, pVl, 0);
    gemm_bias_kernel<<<dim3(256 / 64, ROWS / 64), 256>>>(pCn, W_cv,  b_cv,  nullptr, ROWS, CD, 256,
                                                         pVh, pVl, 64);

    // 3. RMS norms + split-bf16 Q/K writes (qscale folded into Q)
    rms512_split_kernel<<<ROWS, 256>>>(pqkv, rms_v, pQh, pQl, pKh, pKl, 0);
    rms512_split_kernel<<<ROWS, 256>>>(pqkc, rms_c, pQh, pQl, pKh, pKl, 64);

    // 4. Attention (tensor cores, split-bf16, occ=2)
    cudaFuncSetAttribute(attn_kernel, cudaFuncAttributeMaxDynamicSharedMemorySize,
                         (int)sizeof(AttnSmem));
    attn_kernel<<<dim3(NN / 64, BB * HH), 256, sizeof(AttnSmem)>>>(pQh, pQl, pKh, pKl, pVh, pVl,
                                                                   povp, pocp);

    // 5. Output projections (write directly into d_out)
    gemm_bias_kernel<<<dim3(256 / 64, ROWS / 64), 256>>>(povp, W_ov, b_ov, out_v, ROWS, INNER, VD,
                                                         nullptr, nullptr, 0);
    gemm_bias_kernel<<<dim3(64 / 64,  ROWS / 64), 256>>>(pocp, W_oc, b_oc, out_c, ROWS, INNER, CD,
                                                         nullptr, nullptr, 0);
}

// round 8
// speedup vs baseline: 2.1148x; 2.1148x over previous
#include <cuda_runtime.h>
#include <cuda_bf16.h>
#include <math.h>
#include <stdint.h>

// Problem constants
#define BB 4
#define NN 2048
#define VD 256
#define CD 64
#define HH 4
#define DD 64
#define INNER 256
#define ROWS (BB * NN)   // 8192

// ---------------- scratch (device globals; no allocation allowed) ----------
__device__ float g_Vn[ROWS * VD];          // LN(V)
__device__ float g_Cn[ROWS * CD];          // LN(C)
__device__ float g_qkv[ROWS * 2 * INNER];  // Vn @ W_vqk + b   (pre-rms)
__device__ float g_qkc[ROWS * 2 * INNER];  // Cn @ W_cqk + b   (pre-rms)
__device__ float g_ovp[ROWS * INNER];      // attn @ vv (pre out-proj)
__device__ float g_ocp[ROWS * INNER];      // attn @ vc (pre out-proj)

// pre-split bf16 hi/lo buffers, head-interleaved: [row][h*128 + d], d in 0..127
// d<64 = v-channel part, d>=64 = c-channel part. Q has qscale folded in.
__device__ __nv_bfloat16 g_Qh[ROWS * 512];
__device__ __nv_bfloat16 g_Ql[ROWS * 512];
__device__ __nv_bfloat16 g_Kh[ROWS * 512];
__device__ __nv_bfloat16 g_Kl[ROWS * 512];
__device__ __nv_bfloat16 g_Vh[ROWS * 512];
__device__ __nv_bfloat16 g_Vl[ROWS * 512];

// ---------------- LayerNorm -------------------------------------------------
template <int DIM>
__global__ void ln_kernel(const float* __restrict__ x, const float* __restrict__ g,
                          const float* __restrict__ b, float* __restrict__ out) {
    constexpr int NW = DIM / 32;
    __shared__ float red[NW];
    int row = blockIdx.x;
    int t = threadIdx.x;
    float v = x[row * DIM + t];

    float s = v;
    #pragma unroll
    for (int o = 16; o; o >>= 1) s += __shfl_xor_sync(0xFFFFFFFFu, s, o);
    if ((t & 31) == 0) red[t >> 5] = s;
    __syncthreads();
    float tot = 0.f;
    #pragma unroll
    for (int i = 0; i < NW; i++) tot += red[i];
    float mean = tot / (float)DIM;
    __syncthreads();

    float d = v - mean;
    float s2 = d * d;
    #pragma unroll
    for (int o = 16; o; o >>= 1) s2 += __shfl_xor_sync(0xFFFFFFFFu, s2, o);
    if ((t & 31) == 0) red[t >> 5] = s2;
    __syncthreads();
    float var = 0.f;
    #pragma unroll
    for (int i = 0; i < NW; i++) var += red[i];
    var /= (float)DIM;

    out[row * DIM + t] = d * rsqrtf(var + 1e-5f) * g[t] + b[t];
}

// ---- RMSNorm over 512 + split-bf16 write to head-interleaved Q/K buffers ---
__global__ void rms512_split_kernel(const float* __restrict__ x, const float* __restrict__ s,
                                    __nv_bfloat16* __restrict__ Qh, __nv_bfloat16* __restrict__ Ql,
                                    __nv_bfloat16* __restrict__ Kh, __nv_bfloat16* __restrict__ Kl,
                                    int coff) {
    __shared__ float red[8];
    int row = blockIdx.x;
    int t = threadIdx.x;   // 256 threads, 2 elems each
    const float* xr = x + (size_t)row * 512;
    float a = xr[t], c = xr[t + 256];
    float ss = a * a + c * c;
    #pragma unroll
    for (int o = 16; o; o >>= 1) ss += __shfl_xor_sync(0xFFFFFFFFu, ss, o);
    if ((t & 31) == 0) red[t >> 5] = ss;
    __syncthreads();
    float tot = 0.f;
    #pragma unroll
    for (int i = 0; i < 8; i++) tot += red[i];
    float r = rsqrtf(tot / 512.f + 1e-6f);

    float qv = a * r * s[t] * 0.125f;          // qscale folded in
    float kv = c * r * s[t + 256];
    int h = t >> 6, d = t & 63;
    size_t di = (size_t)row * 512 + h * 128 + coff + d;
    float qh = __bfloat162float(__float2bfloat16_rn(qv));
    Qh[di] = __float2bfloat16_rn(qh);
    Ql[di] = __float2bfloat16_rn(qv - qh);
    float kh = __bfloat162float(__float2bfloat16_rn(kv));
    Kh[di] = __float2bfloat16_rn(kh);
    Kl[di] = __float2bfloat16_rn(kv - kh);
}

// ---------------- Tiled SGEMM + bias -----------------------------------------
// If bh != nullptr: write split-bf16 to bh/bl at head-interleaved dst
// col = (n>>6)*128 + coff + (n&63), row stride 512.
__global__ void gemm_bias_kernel(const float* __restrict__ A, const float* __restrict__ W,
                                 const float* __restrict__ bias, float* __restrict__ C,
                                 int M, int K, int Nc,
                                 __nv_bfloat16* __restrict__ bh,
                                 __nv_bfloat16* __restrict__ bl, int coff) {
    __shared__ float As[16][64];   // [k][m]
    __shared__ float Ws[16][64];   // [k][n]
    int bm0 = blockIdx.y * 64;
    int bn0 = blockIdx.x * 64;
    int tid = threadIdx.x;
    int tx = tid & 15, ty = tid >> 4;

    float acc[4][4] = {};

    int arow  = tid >> 2;
    int acol4 = (tid & 3) * 4;
    int wrow  = tid >> 4;
    int wcol4 = (tid & 15) * 4;

    for (int k0 = 0; k0 < K; k0 += 16) {
        float4 av = *(const float4*)&A[(size_t)(bm0 + arow) * K + k0 + acol4];
        As[acol4 + 0][arow] = av.x;
        As[acol4 + 1][arow] = av.y;
        As[acol4 + 2][arow] = av.z;
        As[acol4 + 3][arow] = av.w;
        float4 wv = *(const float4*)&W[(size_t)(k0 + wrow) * Nc + bn0 + wcol4];
        *(float4*)&Ws[wrow][wcol4] = wv;
        __syncthreads();
        #pragma unroll
        for (int k = 0; k < 16; k++) {
            float4 a = *(const float4*)&As[k][ty * 4];
            float4 w = *(const float4*)&Ws[k][tx * 4];
            acc[0][0] += a.x * w.x; acc[0][1] += a.x * w.y; acc[0][2] += a.x * w.z; acc[0][3] += a.x * w.w;
            acc[1][0] += a.y * w.x; acc[1][1] += a.y * w.y; acc[1][2] += a.y * w.z; acc[1][3] += a.y * w.w;
            acc[2][0] += a.z * w.x; acc[2][1] += a.z * w.y; acc[2][2] += a.z * w.z; acc[2][3] += a.z * w.w;
            acc[3][0] += a.w * w.x; acc[3][1] += a.w * w.y; acc[3][2] += a.w * w.z; acc[3][3] += a.w * w.w;
        }
        __syncthreads();
    }
    if (bh) {
        #pragma unroll
        for (int i = 0; i < 4; i++) {
            int m = bm0 + ty * 4 + i;
            #pragma unroll
            for (int j = 0; j < 4; j++) {
                int n = bn0 + tx * 4 + j;
                float v = acc[i][j] + bias[n];
                float vh = __bfloat162float(__float2bfloat16_rn(v));
                size_t di = (size_t)m * 512 + ((n >> 6) * 128 + coff + (n & 63));
                bh[di] = __float2bfloat16_rn(vh);
                bl[di] = __float2bfloat16_rn(v - vh);
            }
        }
    } else {
        #pragma unroll
        for (int i = 0; i < 4; i++) {
            int m = bm0 + ty * 4 + i;
            #pragma unroll
            for (int j = 0; j < 4; j++) {
                int n = bn0 + tx * 4 + j;
                C[(size_t)m * Nc + n] = acc[i][j] + bias[n];
            }
        }
    }
}

// ---------------- Tensor-core attention (FA2 register softmax) --------------
// TQ=64, 4 warps x 16 rows; each warp owns ALL 64 S columns of its rows.
// S stays in MMA accumulators; P split to bf16 hi/lo in registers and fed
// directly as A-operand of PV. No S/P smem, 2 syncs per KV tile.

#define LDSM_X4(r0,r1,r2,r3,addr) \
    asm volatile("ldmatrix.sync.aligned.m8n8.x4.shared.b16 {%0,%1,%2,%3}, [%4];" \
        : "=r"(r0),"=r"(r1),"=r"(r2),"=r"(r3) : "r"(addr))

#define LDSM_X4_T(r0,r1,r2,r3,addr) \
    asm volatile("ldmatrix.sync.aligned.m8n8.x4.trans.shared.b16 {%0,%1,%2,%3}, [%4];" \
        : "=r"(r0),"=r"(r1),"=r"(r2),"=r"(r3) : "r"(addr))

#define MMA_BF16(C, A, b0_, b1_) \
    asm volatile("mma.sync.aligned.m16n8k16.row.col.f32.bf16.bf16.f32 " \
        "{%0,%1,%2,%3}, {%4,%5,%6,%7}, {%8,%9}, {%0,%1,%2,%3};" \
        : "+f"((C)[0]), "+f"((C)[1]), "+f"((C)[2]), "+f"((C)[3]) \
        : "r"((A)[0]), "r"((A)[1]), "r"((A)[2]), "r"((A)[3]), "r"(b0_), "r"(b1_))

struct AttnSmem {
    __nv_bfloat16 Qh[64][136];
    __nv_bfloat16 Ql[64][136];
    __nv_bfloat16 Kh[64][136];
    __nv_bfloat16 Kl[64][136];
    __nv_bfloat16 Vh[64][136];
    __nv_bfloat16 Vl[64][136];
};  // 104,448 B -> 2 CTAs/SM

static __device__ __forceinline__ uint32_t smem_u32(const void* p) {
    return (uint32_t)__cvta_generic_to_shared(p);
}

static __device__ __forceinline__ void split_pack2(float a, float b,
                                                   uint32_t& hi, uint32_t& lo) {
    float ah = __bfloat162float(__float2bfloat16_rn(a));
    float bh2 = __bfloat162float(__float2bfloat16_rn(b));
    __nv_bfloat162 h2 = __floats2bfloat162_rn(ah, bh2);
    __nv_bfloat162 l2 = __floats2bfloat162_rn(a - ah, b - bh2);
    hi = *(uint32_t*)&h2;
    lo = *(uint32_t*)&l2;
}

__global__ void __launch_bounds__(128, 2)
attn_kernel(const __nv_bfloat16* __restrict__ gQh, const __nv_bfloat16* __restrict__ gQl,
            const __nv_bfloat16* __restrict__ gKh, const __nv_bfloat16* __restrict__ gKl,
            const __nv_bfloat16* __restrict__ gVh, const __nv_bfloat16* __restrict__ gVl,
            float* __restrict__ ovp, float* __restrict__ ocp) {
    extern __shared__ char smraw[];
    AttnSmem& sm = *(AttnSmem*)smraw;
    int tid = threadIdx.x;
    int lane = tid & 31;
    int wid = tid >> 5;       // 0..3
    int m0 = wid * 16;
    int g = lane >> 2, t4 = lane & 3;

    int bh_ = blockIdx.y;
    int b = bh_ >> 2;
    int h = bh_ & 3;
    int n0q = blockIdx.x * 64;

    const uint32_t HL = 64 * 136 * 2;   // hi -> lo byte offset (all buffers)

    // ---- Fill Q tile (hi+lo), pure uint4 copies ----
    for (int idx = tid; idx < 1024; idx += 128) {
        int tok = idx >> 4;
        int c8 = (idx & 15) << 3;
        size_t base = (size_t)(b * NN + n0q + tok) * 512 + h * 128 + c8;
        *(uint4*)&sm.Qh[tok][c8] = *(const uint4*)&gQh[base];
        *(uint4*)&sm.Ql[tok][c8] = *(const uint4*)&gQl[base];
    }

    float m_[2] = {-1e30f, -1e30f};
    float l_[2] = {0.f, 0.f};
    float cO[16][4] = {};     // O: m16 x n128 per warp (16 n8-frags)
    __syncthreads();

    for (int jt = 0; jt < NN / 64; jt++) {
        int kn0 = jt * 64;
        // ---- Fill K, V tiles (hi+lo) ----
        for (int idx = tid; idx < 1024; idx += 128) {
            int tok = idx >> 4;
            int c8 = (idx & 15) << 3;
            size_t base = (size_t)(b * NN + kn0 + tok) * 512 + h * 128 + c8;
            *(uint4*)&sm.Kh[tok][c8] = *(const uint4*)&gKh[base];
            *(uint4*)&sm.Kl[tok][c8] = *(const uint4*)&gKl[base];
            *(uint4*)&sm.Vh[tok][c8] = *(const uint4*)&gVh[base];
            *(uint4*)&sm.Vl[tok][c8] = *(const uint4*)&gVl[base];
        }
        __syncthreads();

        // ---- S = Q @ K^T (m16 x n64 per warp), split-bf16 x3 ----
        float cS[8][4] = {};
        #pragma unroll
        for (int kf = 0; kf < 8; kf++) {
            int k0 = kf * 16;
            uint32_t ah[4], al[4];
            uint32_t aaddr = smem_u32(&sm.Qh[m0 + (lane & 15)][k0 + (lane >> 4) * 8]);
            LDSM_X4(ah[0], ah[1], ah[2], ah[3], aaddr);
            LDSM_X4(al[0], al[1], al[2], al[3], aaddr + HL);
            #pragma unroll
            for (int nb = 0; nb < 4; nb++) {
                uint32_t bh0, bh1, bh2, bh3, bl0, bl1, bl2, bl3;
                uint32_t baddr = smem_u32(&sm.Kh[nb * 16 + ((lane >> 4) & 1) * 8 + (lane & 7)]
                                                [k0 + ((lane >> 3) & 1) * 8]);
                LDSM_X4(bh0, bh1, bh2, bh3, baddr);
                LDSM_X4(bl0, bl1, bl2, bl3, baddr + HL);
                MMA_BF16(cS[2 * nb], ah, bh0, bh1);
                MMA_BF16(cS[2 * nb], ah, bl0, bl1);
                MMA_BF16(cS[2 * nb], al, bh0, bh1);
                MMA_BF16(cS[2 * nb + 1], ah, bh2, bh3);
                MMA_BF16(cS[2 * nb + 1], ah, bl2, bl3);
                MMA_BF16(cS[2 * nb + 1], al, bh2, bh3);
            }
        }

        // ---- Register softmax (rows g and g+8; cols via intra-quad shuffles) ----
        #pragma unroll
        for (int r = 0; r < 2; r++) {
            float mx = -1e30f;
            #pragma unroll
            for (int n = 0; n < 8; n++)
                mx = fmaxf(mx, fmaxf(cS[n][2 * r], cS[n][2 * r + 1]));
            mx = fmaxf(mx, __shfl_xor_sync(0xFFFFFFFFu, mx, 1));
            mx = fmaxf(mx, __shfl_xor_sync(0xFFFFFFFFu, mx, 2));
            float m_new = fmaxf(m_[r], mx);
            float alpha = __expf(m_[r] - m_new);
            float sum = 0.f;
            #pragma unroll
            for (int n = 0; n < 8; n++) {
                float p0 = __expf(cS[n][2 * r]     - m_new);
                float p1 = __expf(cS[n][2 * r + 1] - m_new);
                cS[n][2 * r] = p0; cS[n][2 * r + 1] = p1;
                sum += p0 + p1;
            }
            sum += __shfl_xor_sync(0xFFFFFFFFu, sum, 1);
            sum += __shfl_xor_sync(0xFFFFFFFFu, sum, 2);
            l_[r] = l_[r] * alpha + sum;
            m_[r] = m_new;
            #pragma unroll
            for (int nf = 0; nf < 16; nf++) {
                cO[nf][2 * r]     *= alpha;
                cO[nf][2 * r + 1] *= alpha;
            }
        }

        // ---- Pack P fragments (hi/lo) directly from cS registers ----
        // A-frag for k-frag j: a0=(g,2t4|2t4+1)=cS[2j][0,1]  a1=(g+8)=cS[2j][2,3]
        //                      a2=cS[2j+1][0,1]              a3=cS[2j+1][2,3]
        uint32_t PhA[4][4], PlA[4][4];
        #pragma unroll
        for (int j = 0; j < 4; j++) {
            split_pack2(cS[2 * j][0],     cS[2 * j][1],     PhA[j][0], PlA[j][0]);
            split_pack2(cS[2 * j][2],     cS[2 * j][3],     PhA[j][1], PlA[j][1]);
            split_pack2(cS[2 * j + 1][0], cS[2 * j + 1][1], PhA[j][2], PlA[j][2]);
            split_pack2(cS[2 * j + 1][2], cS[2 * j + 1][3], PhA[j][3], PlA[j][3]);
        }

        // ---- O += P @ V (m16 x n128 per warp), split x3 ----
        #pragma unroll
        for (int j = 0; j < 4; j++) {          // k-frag: tokens 16j..16j+15
            #pragma unroll
            for (int nh = 0; nh < 8; nh++) {   // 16-col V groups
                uint32_t bh0, bh1, bh2, bh3, bl0, bl1, bl2, bl3;
                uint32_t baddr = smem_u32(&sm.Vh[j * 16 + ((lane >> 3) & 1) * 8 + (lane & 7)]
                                                [nh * 16 + (lane >> 4) * 8]);
                LDSM_X4_T(bh0, bh1, bh2, bh3, baddr);
                LDSM_X4_T(bl0, bl1, bl2, bl3, baddr + HL);
                MMA_BF16(cO[2 * nh], PhA[j], bh0, bh1);
                MMA_BF16(cO[2 * nh], PhA[j], bl0, bl1);
                MMA_BF16(cO[2 * nh], PlA[j], bh0, bh1);
                MMA_BF16(cO[2 * nh + 1], PhA[j], bh2, bh3);
                MMA_BF16(cO[2 * nh + 1], PhA[j], bl2, bl3);
                MMA_BF16(cO[2 * nh + 1], PlA[j], bh2, bh3);
            }
        }
        __syncthreads();   // K/V free for next tile
    }

    // ---- Epilogue: normalize, write ovp / ocp ----
    float li0 = 1.f / l_[0];
    float li1 = 1.f / l_[1];
    size_t row0 = (size_t)(b * NN + n0q + m0 + g);
    size_t row1 = row0 + 8;
    #pragma unroll
    for (int nf = 0; nf < 16; nf++) {
        int c = nf * 8 + t4 * 2;
        float2 o0 = make_float2(cO[nf][0] * li0, cO[nf][1] * li0);
        float2 o1 = make_float2(cO[nf][2] * li1, cO[nf][3] * li1);
        if (c < 64) {
            *(float2*)&ovp[row0 * 256 + h * 64 + c] = o0;
            *(float2*)&ovp[row1 * 256 + h * 64 + c] = o1;
        } else {
            *(float2*)&ocp[row0 * 256 + h * 64 + (c - 64)] = o0;
            *(float2*)&ocp[row1 * 256 + h * 64 + (c - 64)] = o1;
        }
    }
}

// ---------------- launch ----------------------------------------------------
extern "C" void kernel_launch(void* const* d_in, const int* in_sizes, int n_in,
                              void* d_out, int out_size) {
    const float* V     = (const float*)d_in[0];
    const float* C     = (const float*)d_in[1];
    const float* vn_g  = (const float*)d_in[2];
    const float* vn_b  = (const float*)d_in[3];
    const float* cn_g  = (const float*)d_in[4];
    const float* cn_b  = (const float*)d_in[5];
    const float* W_vqk = (const float*)d_in[6];
    const float* b_vqk = (const float*)d_in[7];
    const float* rms_v = (const float*)d_in[8];
    const float* W_cqk = (const float*)d_in[9];
    const float* b_cqk = (const float*)d_in[10];
    const float* rms_c = (const float*)d_in[11];
    const float* W_vv  = (const float*)d_in[12];
    const float* b_vv  = (const float*)d_in[13];
    const float* W_cv  = (const float*)d_in[14];
    const float* b_cv  = (const float*)d_in[15];
    const float* W_ov  = (const float*)d_in[16];
    const float* b_ov  = (const float*)d_in[17];
    const float* W_oc  = (const float*)d_in[18];
    const float* b_oc  = (const float*)d_in[19];

    float* out_v = (float*)d_out;                    // (B,N,VD)
    float* out_c = out_v + (size_t)ROWS * VD;        // (B,N,CD)

    float *pVn, *pCn, *pqkv, *pqkc, *povp, *pocp;
    __nv_bfloat16 *pQh, *pQl, *pKh, *pKl, *pVh, *pVl;
    cudaGetSymbolAddress((void**)&pVn,  g_Vn);
    cudaGetSymbolAddress((void**)&pCn,  g_Cn);
    cudaGetSymbolAddress((void**)&pqkv, g_qkv);
    cudaGetSymbolAddress((void**)&pqkc, g_qkc);
    cudaGetSymbolAddress((void**)&povp, g_ovp);
    cudaGetSymbolAddress((void**)&pocp, g_ocp);
    cudaGetSymbolAddress((void**)&pQh, g_Qh);
    cudaGetSymbolAddress((void**)&pQl, g_Ql);
    cudaGetSymbolAddress((void**)&pKh, g_Kh);
    cudaGetSymbolAddress((void**)&pKl, g_Kl);
    cudaGetSymbolAddress((void**)&pVh, g_Vh);
    cudaGetSymbolAddress((void**)&pVl, g_Vl);

    // 1. LayerNorms
    ln_kernel<VD><<<ROWS, VD>>>(V, vn_g, vn_b, pVn);
    ln_kernel<CD><<<ROWS, CD>>>(C, cn_g, cn_b, pCn);

    // 2. Projections (qk -> fp32 for rms; v -> split-bf16 directly)
    gemm_bias_kernel<<<dim3(512 / 64, ROWS / 64), 256>>>(pVn, W_vqk, b_vqk, pqkv, ROWS, VD, 512,
                                                         nullptr, nullptr, 0);
    gemm_bias_kernel<<<dim3(512 / 64, ROWS / 64), 256>>>(pCn, W_cqk, b_cqk, pqkc, ROWS, CD, 512,
                                                         nullptr, nullptr, 0);
    gemm_bias_kernel<<<dim3(256 / 64, ROWS / 64), 256>>>(pVn, W_vv,  b_vv,  nullptr, ROWS, VD, 256,
                                                         pVh, pVl, 0);
    gemm_bias_kernel<<<dim3(256 / 64, ROWS / 64), 256>>>(pCn, W_cv,  b_cv,  nullptr, ROWS, CD, 256,
                                                         pVh, pVl, 64);

    // 3. RMS norms + split-bf16 Q/K writes (qscale folded into Q)
    rms512_split_kernel<<<ROWS, 256>>>(pqkv, rms_v, pQh, pQl, pKh, pKl, 0);
    rms512_split_kernel<<<ROWS, 256>>>(pqkc, rms_c, pQh, pQl, pKh, pKl, 64);

    // 4. Attention (FA2 register softmax, split-bf16, occ=2)
    cudaFuncSetAttribute(attn_kernel, cudaFuncAttributeMaxDynamicSharedMemorySize,
                         (int)sizeof(AttnSmem));
    attn_kernel<<<dim3(NN / 64, BB * HH), 128, sizeof(AttnSmem)>>>(pQh, pQl, pKh, pKl, pVh, pVl,
                                                                   povp, pocp);

    // 5. Output projections (write directly into d_out)
    gemm_bias_kernel<<<dim3(256 / 64, ROWS / 64), 256>>>(povp, W_ov, b_ov, out_v, ROWS, INNER, VD,
                                                         nullptr, nullptr, 0);
    gemm_bias_kernel<<<dim3(64 / 64,  ROWS / 64), 256>>>(pocp, W_oc, b_oc, out_c, ROWS, INNER, CD,
                                                         nullptr, nullptr, 0);
}

// round 9
// speedup vs baseline: 2.6128x; 1.2355x over previous
#include <cuda_runtime.h>
#include <cuda_bf16.h>
#include <math.h>
#include <stdint.h>

// Problem constants
#define BB 4
#define NN 2048
#define VD 256
#define CD 64
#define HH 4
#define DD 64
#define INNER 256
#define ROWS (BB * NN)   // 8192

typedef __nv_bfloat16 bf16;

// ---------------- scratch (device globals; no allocation allowed) ----------
__device__ float g_qkv[ROWS * 2 * INNER];  // Vn @ W_vqk + b   (pre-rms, fp32)
__device__ float g_qkc[ROWS * 2 * INNER];  // Cn @ W_cqk + b   (pre-rms, fp32)

// split-bf16 activations
__device__ bf16 g_Vnh[ROWS * VD];
__device__ bf16 g_Vnl[ROWS * VD];
__device__ bf16 g_Cnh[ROWS * CD];
__device__ bf16 g_Cnl[ROWS * CD];
__device__ bf16 g_ovph[ROWS * INNER];
__device__ bf16 g_ovpl[ROWS * INNER];
__device__ bf16 g_ocph[ROWS * INNER];
__device__ bf16 g_ocpl[ROWS * INNER];

// split-bf16 weights
__device__ bf16 g_Wvqk_h[VD * 512];
__device__ bf16 g_Wvqk_l[VD * 512];
__device__ bf16 g_Wcqk_h[CD * 512];
__device__ bf16 g_Wcqk_l[CD * 512];
__device__ bf16 g_Wvv_h[VD * INNER];
__device__ bf16 g_Wvv_l[VD * INNER];
__device__ bf16 g_Wcv_h[CD * INNER];
__device__ bf16 g_Wcv_l[CD * INNER];
__device__ bf16 g_Wov_h[INNER * VD];
__device__ bf16 g_Wov_l[INNER * VD];
__device__ bf16 g_Woc_h[INNER * CD];
__device__ bf16 g_Woc_l[INNER * CD];

// pre-split bf16 hi/lo Q/K/V, head-interleaved: [row][h*128 + d], d 0..127
// d<64 = v-channel, d>=64 = c-channel. Q has qscale folded in.
__device__ bf16 g_Qh[ROWS * 512];
__device__ bf16 g_Ql[ROWS * 512];
__device__ bf16 g_Kh[ROWS * 512];
__device__ bf16 g_Kl[ROWS * 512];
__device__ bf16 g_Vh[ROWS * 512];
__device__ bf16 g_Vl[ROWS * 512];

// ---------------- helpers ---------------------------------------------------
static __device__ __forceinline__ uint32_t smem_u32(const void* p) {
    return (uint32_t)__cvta_generic_to_shared(p);
}

static __device__ __forceinline__ void split1(float v, bf16& h, bf16& l) {
    float vh = __bfloat162float(__float2bfloat16_rn(v));
    h = __float2bfloat16_rn(vh);
    l = __float2bfloat16_rn(v - vh);
}

static __device__ __forceinline__ void split_pack2(float a, float b,
                                                   uint32_t& hi, uint32_t& lo) {
    float ah = __bfloat162float(__float2bfloat16_rn(a));
    float bh2 = __bfloat162float(__float2bfloat16_rn(b));
    __nv_bfloat162 h2 = __floats2bfloat162_rn(ah, bh2);
    __nv_bfloat162 l2 = __floats2bfloat162_rn(a - ah, b - bh2);
    hi = *(uint32_t*)&h2;
    lo = *(uint32_t*)&l2;
}

#define LDSM_X4(r0,r1,r2,r3,addr) \
    asm volatile("ldmatrix.sync.aligned.m8n8.x4.shared.b16 {%0,%1,%2,%3}, [%4];" \
        : "=r"(r0),"=r"(r1),"=r"(r2),"=r"(r3) : "r"(addr))

#define LDSM_X4_T(r0,r1,r2,r3,addr) \
    asm volatile("ldmatrix.sync.aligned.m8n8.x4.trans.shared.b16 {%0,%1,%2,%3}, [%4];" \
        : "=r"(r0),"=r"(r1),"=r"(r2),"=r"(r3) : "r"(addr))

#define MMA_BF16(C, A, b0_, b1_) \
    asm volatile("mma.sync.aligned.m16n8k16.row.col.f32.bf16.bf16.f32 " \
        "{%0,%1,%2,%3}, {%4,%5,%6,%7}, {%8,%9}, {%0,%1,%2,%3};" \
        : "+f"((C)[0]), "+f"((C)[1]), "+f"((C)[2]), "+f"((C)[3]) \
        : "r"((A)[0]), "r"((A)[1]), "r"((A)[2]), "r"((A)[3]), "r"(b0_), "r"(b1_))

// ---------------- LayerNorm + split-bf16 output ------------------------------
template <int DIM>
__global__ void ln_split_kernel(const float* __restrict__ x, const float* __restrict__ g,
                                const float* __restrict__ b,
                                bf16* __restrict__ oh, bf16* __restrict__ ol) {
    constexpr int NW = DIM / 32;
    __shared__ float red[NW];
    int row = blockIdx.x;
    int t = threadIdx.x;
    float v = x[(size_t)row * DIM + t];

    float s = v;
    #pragma unroll
    for (int o = 16; o; o >>= 1) s += __shfl_xor_sync(0xFFFFFFFFu, s, o);
    if ((t & 31) == 0) red[t >> 5] = s;
    __syncthreads();
    float tot = 0.f;
    #pragma unroll
    for (int i = 0; i < NW; i++) tot += red[i];
    float mean = tot / (float)DIM;
    __syncthreads();

    float d = v - mean;
    float s2 = d * d;
    #pragma unroll
    for (int o = 16; o; o >>= 1) s2 += __shfl_xor_sync(0xFFFFFFFFu, s2, o);
    if ((t & 31) == 0) red[t >> 5] = s2;
    __syncthreads();
    float var = 0.f;
    #pragma unroll
    for (int i = 0; i < NW; i++) var += red[i];
    var /= (float)DIM;

    float out = d * rsqrtf(var + 1e-5f) * g[t] + b[t];
    split1(out, oh[(size_t)row * DIM + t], ol[(size_t)row * DIM + t]);
}

// ---------------- weight split ----------------------------------------------
__global__ void splitw_kernel(const float* __restrict__ s, bf16* __restrict__ h,
                              bf16* __restrict__ l, int n) {
    int i = blockIdx.x * 256 + threadIdx.x;
    if (i < n) split1(s[i], h[i], l[i]);
}

// ---- RMSNorm over 512 + split-bf16 write to head-interleaved Q/K buffers ---
__global__ void rms512_split_kernel(const float* __restrict__ x, const float* __restrict__ s,
                                    bf16* __restrict__ Qh, bf16* __restrict__ Ql,
                                    bf16* __restrict__ Kh, bf16* __restrict__ Kl,
                                    int coff) {
    __shared__ float red[8];
    int row = blockIdx.x;
    int t = threadIdx.x;   // 256 threads, 2 elems each
    const float* xr = x + (size_t)row * 512;
    float a = xr[t], c = xr[t + 256];
    float ss = a * a + c * c;
    #pragma unroll
    for (int o = 16; o; o >>= 1) ss += __shfl_xor_sync(0xFFFFFFFFu, ss, o);
    if ((t & 31) == 0) red[t >> 5] = ss;
    __syncthreads();
    float tot = 0.f;
    #pragma unroll
    for (int i = 0; i < 8; i++) tot += red[i];
    float r = rsqrtf(tot / 512.f + 1e-6f);

    float qv = a * r * s[t] * 0.125f;          // qscale folded in
    float kv = c * r * s[t + 256];
    int h = t >> 6, d = t & 63;
    size_t di = (size_t)row * 512 + h * 128 + coff + d;
    split1(qv, Qh[di], Ql[di]);
    split1(kv, Kh[di], Kl[di]);
}

// ---------------- Tensor-core GEMM (split-bf16 x3) ---------------------------
// C(M x Nc) = A(M x K) @ B(K x Nc) + bias.  Tiles 64x64x64; 128 thr = 4 warps,
// each warp m16 x n64. A-frag pattern = attention Q/P; B via trans-ldmatrix
// (= attention V pattern). Epilogue: fp32 C, or split-bf16 head-interleaved.
struct GemmSmem {
    bf16 Ah[64][72];
    bf16 Al[64][72];
    bf16 Bh[64][72];
    bf16 Bl[64][72];
};  // 36,864 B

__global__ void __launch_bounds__(128)
mma_gemm_kernel(const bf16* __restrict__ Ah_, const bf16* __restrict__ Al_,
                const bf16* __restrict__ Bh_, const bf16* __restrict__ Bl_,
                const float* __restrict__ bias, float* __restrict__ C,
                int K, int Nc,
                bf16* __restrict__ oh, bf16* __restrict__ ol, int coff) {
    __shared__ GemmSmem sm;
    int tid = threadIdx.x;
    int lane = tid & 31;
    int wid = tid >> 5;
    int m0 = wid * 16;
    int g = lane >> 2, t4 = lane & 3;
    int bm0 = blockIdx.y * 64;
    int bn0 = blockIdx.x * 64;

    const uint32_t HL = 64 * 72 * 2;
    float cC[8][4] = {};

    for (int k0 = 0; k0 < K; k0 += 64) {
        for (int idx = tid; idx < 512; idx += 128) {
            int tok = idx >> 3;
            int c8 = (idx & 7) << 3;
            size_t abase = (size_t)(bm0 + tok) * K + k0 + c8;
            *(uint4*)&sm.Ah[tok][c8] = *(const uint4*)&Ah_[abase];
            *(uint4*)&sm.Al[tok][c8] = *(const uint4*)&Al_[abase];
            size_t bbase = (size_t)(k0 + tok) * Nc + bn0 + c8;
            *(uint4*)&sm.Bh[tok][c8] = *(const uint4*)&Bh_[bbase];
            *(uint4*)&sm.Bl[tok][c8] = *(const uint4*)&Bl_[bbase];
        }
        __syncthreads();

        #pragma unroll
        for (int j = 0; j < 4; j++) {            // k-frags (16 each)
            uint32_t ah[4], al[4];
            uint32_t aaddr = smem_u32(&sm.Ah[m0 + (lane & 15)][j * 16 + (lane >> 4) * 8]);
            LDSM_X4(ah[0], ah[1], ah[2], ah[3], aaddr);
            LDSM_X4(al[0], al[1], al[2], al[3], aaddr + HL);
            #pragma unroll
            for (int nh = 0; nh < 4; nh++) {     // n16 groups
                uint32_t bh0, bh1, bh2, bh3, bl0, bl1, bl2, bl3;
                uint32_t baddr = smem_u32(&sm.Bh[j * 16 + ((lane >> 3) & 1) * 8 + (lane & 7)]
                                                [nh * 16 + (lane >> 4) * 8]);
                LDSM_X4_T(bh0, bh1, bh2, bh3, baddr);
                LDSM_X4_T(bl0, bl1, bl2, bl3, baddr + HL);
                MMA_BF16(cC[2 * nh], ah, bh0, bh1);
                MMA_BF16(cC[2 * nh], ah, bl0, bl1);
                MMA_BF16(cC[2 * nh], al, bh0, bh1);
                MMA_BF16(cC[2 * nh + 1], ah, bh2, bh3);
                MMA_BF16(cC[2 * nh + 1], ah, bl2, bl3);
                MMA_BF16(cC[2 * nh + 1], al, bh2, bh3);
            }
        }
        __syncthreads();
    }

    // epilogue: rows bm0+m0+g (c0,c1) and +8 (c2,c3); cols bn0 + nf*8 + t4*2
    int r0 = bm0 + m0 + g;
    if (oh) {
        #pragma unroll
        for (int nf = 0; nf < 8; nf++) {
            int n = bn0 + nf * 8 + t4 * 2;
            float b0 = bias[n], b1 = bias[n + 1];
            size_t di0 = (size_t)r0 * 512 + ((n >> 6) * 128 + coff + (n & 63));
            size_t di1 = (size_t)(r0 + 8) * 512 + ((n >> 6) * 128 + coff + (n & 63));
            uint32_t h0, l0, h1, l1;
            split_pack2(cC[nf][0] + b0, cC[nf][1] + b1, h0, l0);
            split_pack2(cC[nf][2] + b0, cC[nf][3] + b1, h1, l1);
            *(uint32_t*)&oh[di0] = h0; *(uint32_t*)&ol[di0] = l0;
            *(uint32_t*)&oh[di1] = h1; *(uint32_t*)&ol[di1] = l1;
        }
    } else {
        #pragma unroll
        for (int nf = 0; nf < 8; nf++) {
            int n = bn0 + nf * 8 + t4 * 2;
            float b0 = bias[n], b1 = bias[n + 1];
            *(float2*)&C[(size_t)r0 * Nc + n] =
                make_float2(cC[nf][0] + b0, cC[nf][1] + b1);
            *(float2*)&C[(size_t)(r0 + 8) * Nc + n] =
                make_float2(cC[nf][2] + b0, cC[nf][3] + b1);
        }
    }
}

// ---------------- Tensor-core attention (FA2 register softmax) --------------
struct AttnSmem {
    bf16 Qh[64][136];
    bf16 Ql[64][136];
    bf16 Kh[64][136];
    bf16 Kl[64][136];
    bf16 Vh[64][136];
    bf16 Vl[64][136];
};  // 104,448 B -> 2 CTAs/SM

__global__ void __launch_bounds__(128, 2)
attn_kernel(const bf16* __restrict__ gQh, const bf16* __restrict__ gQl,
            const bf16* __restrict__ gKh, const bf16* __restrict__ gKl,
            const bf16* __restrict__ gVh, const bf16* __restrict__ gVl,
            bf16* __restrict__ ovph, bf16* __restrict__ ovpl,
            bf16* __restrict__ ocph, bf16* __restrict__ ocpl) {
    extern __shared__ char smraw[];
    AttnSmem& sm = *(AttnSmem*)smraw;
    int tid = threadIdx.x;
    int lane = tid & 31;
    int wid = tid >> 5;       // 0..3
    int m0 = wid * 16;
    int g = lane >> 2, t4 = lane & 3;

    int bh_ = blockIdx.y;
    int b = bh_ >> 2;
    int h = bh_ & 3;
    int n0q = blockIdx.x * 64;

    const uint32_t HL = 64 * 136 * 2;

    for (int idx = tid; idx < 1024; idx += 128) {
        int tok = idx >> 4;
        int c8 = (idx & 15) << 3;
        size_t base = (size_t)(b * NN + n0q + tok) * 512 + h * 128 + c8;
        *(uint4*)&sm.Qh[tok][c8] = *(const uint4*)&gQh[base];
        *(uint4*)&sm.Ql[tok][c8] = *(const uint4*)&gQl[base];
    }

    float m_[2] = {-1e30f, -1e30f};
    float l_[2] = {0.f, 0.f};
    float cO[16][4] = {};
    __syncthreads();

    for (int jt = 0; jt < NN / 64; jt++) {
        int kn0 = jt * 64;
        for (int idx = tid; idx < 1024; idx += 128) {
            int tok = idx >> 4;
            int c8 = (idx & 15) << 3;
            size_t base = (size_t)(b * NN + kn0 + tok) * 512 + h * 128 + c8;
            *(uint4*)&sm.Kh[tok][c8] = *(const uint4*)&gKh[base];
            *(uint4*)&sm.Kl[tok][c8] = *(const uint4*)&gKl[base];
            *(uint4*)&sm.Vh[tok][c8] = *(const uint4*)&gVh[base];
            *(uint4*)&sm.Vl[tok][c8] = *(const uint4*)&gVl[base];
        }
        __syncthreads();

        // ---- S = Q @ K^T ----
        float cS[8][4] = {};
        #pragma unroll
        for (int kf = 0; kf < 8; kf++) {
            int k0 = kf * 16;
            uint32_t ah[4], al[4];
            uint32_t aaddr = smem_u32(&sm.Qh[m0 + (lane & 15)][k0 + (lane >> 4) * 8]);
            LDSM_X4(ah[0], ah[1], ah[2], ah[3], aaddr);
            LDSM_X4(al[0], al[1], al[2], al[3], aaddr + HL);
            #pragma unroll
            for (int nb = 0; nb < 4; nb++) {
                uint32_t bh0, bh1, bh2, bh3, bl0, bl1, bl2, bl3;
                uint32_t baddr = smem_u32(&sm.Kh[nb * 16 + ((lane >> 4) & 1) * 8 + (lane & 7)]
                                                [k0 + ((lane >> 3) & 1) * 8]);
                LDSM_X4(bh0, bh1, bh2, bh3, baddr);
                LDSM_X4(bl0, bl1, bl2, bl3, baddr + HL);
                MMA_BF16(cS[2 * nb], ah, bh0, bh1);
                MMA_BF16(cS[2 * nb], ah, bl0, bl1);
                MMA_BF16(cS[2 * nb], al, bh0, bh1);
                MMA_BF16(cS[2 * nb + 1], ah, bh2, bh3);
                MMA_BF16(cS[2 * nb + 1], ah, bl2, bl3);
                MMA_BF16(cS[2 * nb + 1], al, bh2, bh3);
            }
        }

        // ---- Register softmax ----
        #pragma unroll
        for (int r = 0; r < 2; r++) {
            float mx = -1e30f;
            #pragma unroll
            for (int n = 0; n < 8; n++)
                mx = fmaxf(mx, fmaxf(cS[n][2 * r], cS[n][2 * r + 1]));
            mx = fmaxf(mx, __shfl_xor_sync(0xFFFFFFFFu, mx, 1));
            mx = fmaxf(mx, __shfl_xor_sync(0xFFFFFFFFu, mx, 2));
            float m_new = fmaxf(m_[r], mx);
            float alpha = __expf(m_[r] - m_new);
            float sum = 0.f;
            #pragma unroll
            for (int n = 0; n < 8; n++) {
                float p0 = __expf(cS[n][2 * r]     - m_new);
                float p1 = __expf(cS[n][2 * r + 1] - m_new);
                cS[n][2 * r] = p0; cS[n][2 * r + 1] = p1;
                sum += p0 + p1;
            }
            sum += __shfl_xor_sync(0xFFFFFFFFu, sum, 1);
            sum += __shfl_xor_sync(0xFFFFFFFFu, sum, 2);
            l_[r] = l_[r] * alpha + sum;
            m_[r] = m_new;
            #pragma unroll
            for (int nf = 0; nf < 16; nf++) {
                cO[nf][2 * r]     *= alpha;
                cO[nf][2 * r + 1] *= alpha;
            }
        }

        // ---- Pack P fragments ----
        uint32_t PhA[4][4], PlA[4][4];
        #pragma unroll
        for (int j = 0; j < 4; j++) {
            split_pack2(cS[2 * j][0],     cS[2 * j][1],     PhA[j][0], PlA[j][0]);
            split_pack2(cS[2 * j][2],     cS[2 * j][3],     PhA[j][1], PlA[j][1]);
            split_pack2(cS[2 * j + 1][0], cS[2 * j + 1][1], PhA[j][2], PlA[j][2]);
            split_pack2(cS[2 * j + 1][2], cS[2 * j + 1][3], PhA[j][3], PlA[j][3]);
        }

        // ---- O += P @ V ----
        #pragma unroll
        for (int j = 0; j < 4; j++) {
            #pragma unroll
            for (int nh = 0; nh < 8; nh++) {
                uint32_t bh0, bh1, bh2, bh3, bl0, bl1, bl2, bl3;
                uint32_t baddr = smem_u32(&sm.Vh[j * 16 + ((lane >> 3) & 1) * 8 + (lane & 7)]
                                                [nh * 16 + (lane >> 4) * 8]);
                LDSM_X4_T(bh0, bh1, bh2, bh3, baddr);
                LDSM_X4_T(bl0, bl1, bl2, bl3, baddr + HL);
                MMA_BF16(cO[2 * nh], PhA[j], bh0, bh1);
                MMA_BF16(cO[2 * nh], PhA[j], bl0, bl1);
                MMA_BF16(cO[2 * nh], PlA[j], bh0, bh1);
                MMA_BF16(cO[2 * nh + 1], PhA[j], bh2, bh3);
                MMA_BF16(cO[2 * nh + 1], PhA[j], bl2, bl3);
                MMA_BF16(cO[2 * nh + 1], PlA[j], bh2, bh3);
            }
        }
        __syncthreads();
    }

    // ---- Epilogue: normalize, split-bf16 write ----
    float li0 = 1.f / l_[0];
    float li1 = 1.f / l_[1];
    size_t row0 = (size_t)(b * NN + n0q + m0 + g);
    size_t row1 = row0 + 8;
    #pragma unroll
    for (int nf = 0; nf < 16; nf++) {
        int c = nf * 8 + t4 * 2;
        uint32_t h0, l0, h1, l1;
        split_pack2(cO[nf][0] * li0, cO[nf][1] * li0, h0, l0);
        split_pack2(cO[nf][2] * li1, cO[nf][3] * li1, h1, l1);
        if (c < 64) {
            size_t d0 = row0 * 256 + h * 64 + c, d1 = row1 * 256 + h * 64 + c;
            *(uint32_t*)&ovph[d0] = h0; *(uint32_t*)&ovpl[d0] = l0;
            *(uint32_t*)&ovph[d1] = h1; *(uint32_t*)&ovpl[d1] = l1;
        } else {
            size_t d0 = row0 * 256 + h * 64 + (c - 64), d1 = row1 * 256 + h * 64 + (c - 64);
            *(uint32_t*)&ocph[d0] = h0; *(uint32_t*)&ocpl[d0] = l0;
            *(uint32_t*)&ocph[d1] = h1; *(uint32_t*)&ocpl[d1] = l1;
        }
    }
}

// ---------------- launch ----------------------------------------------------
extern "C" void kernel_launch(void* const* d_in, const int* in_sizes, int n_in,
                              void* d_out, int out_size) {
    const float* V     = (const float*)d_in[0];
    const float* C     = (const float*)d_in[1];
    const float* vn_g  = (const float*)d_in[2];
    const float* vn_b  = (const float*)d_in[3];
    const float* cn_g  = (const float*)d_in[4];
    const float* cn_b  = (const float*)d_in[5];
    const float* W_vqk = (const float*)d_in[6];
    const float* b_vqk = (const float*)d_in[7];
    const float* rms_v = (const float*)d_in[8];
    const float* W_cqk = (const float*)d_in[9];
    const float* b_cqk = (const float*)d_in[10];
    const float* rms_c = (const float*)d_in[11];
    const float* W_vv  = (const float*)d_in[12];
    const float* b_vv  = (const float*)d_in[13];
    const float* W_cv  = (const float*)d_in[14];
    const float* b_cv  = (const float*)d_in[15];
    const float* W_ov  = (const float*)d_in[16];
    const float* b_ov  = (const float*)d_in[17];
    const float* W_oc  = (const float*)d_in[18];
    const float* b_oc  = (const float*)d_in[19];

    float* out_v = (float*)d_out;                    // (B,N,VD)
    float* out_c = out_v + (size_t)ROWS * VD;        // (B,N,CD)

    float *pqkv, *pqkc;
    bf16 *pVnh, *pVnl, *pCnh, *pCnl;
    bf16 *pQh, *pQl, *pKh, *pKl, *pVh, *pVl;
    bf16 *povph, *povpl, *pocph, *pocpl;
    bf16 *wvqkh, *wvqkl, *wcqkh, *wcqkl, *wvvh, *wvvl, *wcvh, *wcvl, *wovh, *wovl, *woch, *wocl;
    cudaGetSymbolAddress((void**)&pqkv, g_qkv);
    cudaGetSymbolAddress((void**)&pqkc, g_qkc);
    cudaGetSymbolAddress((void**)&pVnh, g_Vnh);
    cudaGetSymbolAddress((void**)&pVnl, g_Vnl);
    cudaGetSymbolAddress((void**)&pCnh, g_Cnh);
    cudaGetSymbolAddress((void**)&pCnl, g_Cnl);
    cudaGetSymbolAddress((void**)&pQh, g_Qh);
    cudaGetSymbolAddress((void**)&pQl, g_Ql);
    cudaGetSymbolAddress((void**)&pKh, g_Kh);
    cudaGetSymbolAddress((void**)&pKl, g_Kl);
    cudaGetSymbolAddress((void**)&pVh, g_Vh);
    cudaGetSymbolAddress((void**)&pVl, g_Vl);
    cudaGetSymbolAddress((void**)&povph, g_ovph);
    cudaGetSymbolAddress((void**)&povpl, g_ovpl);
    cudaGetSymbolAddress((void**)&pocph, g_ocph);
    cudaGetSymbolAddress((void**)&pocpl, g_ocpl);
    cudaGetSymbolAddress((void**)&wvqkh, g_Wvqk_h);
    cudaGetSymbolAddress((void**)&wvqkl, g_Wvqk_l);
    cudaGetSymbolAddress((void**)&wcqkh, g_Wcqk_h);
    cudaGetSymbolAddress((void**)&wcqkl, g_Wcqk_l);
    cudaGetSymbolAddress((void**)&wvvh, g_Wvv_h);
    cudaGetSymbolAddress((void**)&wvvl, g_Wvv_l);
    cudaGetSymbolAddress((void**)&wcvh, g_Wcv_h);
    cudaGetSymbolAddress((void**)&wcvl, g_Wcv_l);
    cudaGetSymbolAddress((void**)&wovh, g_Wov_h);
    cudaGetSymbolAddress((void**)&wovl, g_Wov_l);
    cudaGetSymbolAddress((void**)&woch, g_Woc_h);
    cudaGetSymbolAddress((void**)&wocl, g_Woc_l);

    // 1. LayerNorms (split-bf16 out)
    ln_split_kernel<VD><<<ROWS, VD>>>(V, vn_g, vn_b, pVnh, pVnl);
    ln_split_kernel<CD><<<ROWS, CD>>>(C, cn_g, cn_b, pCnh, pCnl);

    // 1b. Weight splits
    splitw_kernel<<<(VD * 512 + 255) / 256, 256>>>(W_vqk, wvqkh, wvqkl, VD * 512);
    splitw_kernel<<<(CD * 512 + 255) / 256, 256>>>(W_cqk, wcqkh, wcqkl, CD * 512);
    splitw_kernel<<<(VD * INNER + 255) / 256, 256>>>(W_vv, wvvh, wvvl, VD * INNER);
    splitw_kernel<<<(CD * INNER + 255) / 256, 256>>>(W_cv, wcvh, wcvl, CD * INNER);
    splitw_kernel<<<(INNER * VD + 255) / 256, 256>>>(W_ov, wovh, wovl, INNER * VD);
    splitw_kernel<<<(INNER * CD + 255) / 256, 256>>>(W_oc, woch, wocl, INNER * CD);

    // 2. Projections (tensor-core split GEMM)
    mma_gemm_kernel<<<dim3(512 / 64, ROWS / 64), 128>>>(pVnh, pVnl, wvqkh, wvqkl, b_vqk, pqkv,
                                                        VD, 512, nullptr, nullptr, 0);
    mma_gemm_kernel<<<dim3(512 / 64, ROWS / 64), 128>>>(pCnh, pCnl, wcqkh, wcqkl, b_cqk, pqkc,
                                                        CD, 512, nullptr, nullptr, 0);
    mma_gemm_kernel<<<dim3(256 / 64, ROWS / 64), 128>>>(pVnh, pVnl, wvvh, wvvl, b_vv, nullptr,
                                                        VD, 256, pVh, pVl, 0);
    mma_gemm_kernel<<<dim3(256 / 64, ROWS / 64), 128>>>(pCnh, pCnl, wcvh, wcvl, b_cv, nullptr,
                                                        CD, 256, pVh, pVl, 64);

    // 3. RMS norms + split-bf16 Q/K writes (qscale folded into Q)
    rms512_split_kernel<<<ROWS, 256>>>(pqkv, rms_v, pQh, pQl, pKh, pKl, 0);
    rms512_split_kernel<<<ROWS, 256>>>(pqkc, rms_c, pQh, pQl, pKh, pKl, 64);

    // 4. Attention (FA2 register softmax, split-bf16, occ=2)
    cudaFuncSetAttribute(attn_kernel, cudaFuncAttributeMaxDynamicSharedMemorySize,
                         (int)sizeof(AttnSmem));
    attn_kernel<<<dim3(NN / 64, BB * HH), 128, sizeof(AttnSmem)>>>(pQh, pQl, pKh, pKl, pVh, pVl,
                                                                   povph, povpl, pocph, pocpl);

    // 5. Output projections (tensor-core, write directly into d_out)
    mma_gemm_kernel<<<dim3(256 / 64, ROWS / 64), 128>>>(povph, povpl, wovh, wovl, b_ov, out_v,
                                                        INNER, VD, nullptr, nullptr, 0);
    mma_gemm_kernel<<<dim3(64 / 64, ROWS / 64), 128>>>(pocph, pocpl, woch, wocl, b_oc, out_c,
                                                       INNER, CD, nullptr, nullptr, 0);
}

// round 10
// speedup vs baseline: 2.9676x; 1.1358x over previous
#include <cuda_runtime.h>
#include <cuda_bf16.h>
#include <math.h>
#include <stdint.h>

// Problem constants
#define BB 4
#define NN 2048
#define VD 256
#define CD 64
#define HH 4
#define DD 64
#define INNER 256
#define ROWS (BB * NN)   // 8192

typedef __nv_bfloat16 bf16;

// ---------------- scratch (device globals; no allocation allowed) ----------
__device__ float g_qkv[ROWS * 2 * INNER];  // Vn @ W_vqk + b   (pre-rms, fp32)
__device__ float g_qkc[ROWS * 2 * INNER];  // Cn @ W_cqk + b   (pre-rms, fp32)

// split-bf16 activations
__device__ bf16 g_Vnh[ROWS * VD];
__device__ bf16 g_Vnl[ROWS * VD];
__device__ bf16 g_Cnh[ROWS * CD];
__device__ bf16 g_Cnl[ROWS * CD];
__device__ bf16 g_ovph[ROWS * INNER];
__device__ bf16 g_ovpl[ROWS * INNER];
__device__ bf16 g_ocph[ROWS * INNER];
__device__ bf16 g_ocpl[ROWS * INNER];

// split-bf16 weights
__device__ bf16 g_Wvqk_h[VD * 512];
__device__ bf16 g_Wvqk_l[VD * 512];
__device__ bf16 g_Wcqk_h[CD * 512];
__device__ bf16 g_Wcqk_l[CD * 512];
__device__ bf16 g_Wvv_h[VD * INNER];
__device__ bf16 g_Wvv_l[VD * INNER];
__device__ bf16 g_Wcv_h[CD * INNER];
__device__ bf16 g_Wcv_l[CD * INNER];
__device__ bf16 g_Wov_h[INNER * VD];
__device__ bf16 g_Wov_l[INNER * VD];
__device__ bf16 g_Woc_h[INNER * CD];
__device__ bf16 g_Woc_l[INNER * CD];

// pre-split bf16 hi/lo Q/K/V, head-interleaved: [row][h*128 + d], d 0..127
__device__ bf16 g_Qh[ROWS * 512];
__device__ bf16 g_Ql[ROWS * 512];
__device__ bf16 g_Kh[ROWS * 512];
__device__ bf16 g_Kl[ROWS * 512];
__device__ bf16 g_Vh[ROWS * 512];
__device__ bf16 g_Vl[ROWS * 512];

// ---------------- helpers ---------------------------------------------------
static __device__ __forceinline__ uint32_t smem_u32(const void* p) {
    return (uint32_t)__cvta_generic_to_shared(p);
}

static __device__ __forceinline__ void split1(float v, bf16& h, bf16& l) {
    float vh = __bfloat162float(__float2bfloat16_rn(v));
    h = __float2bfloat16_rn(vh);
    l = __float2bfloat16_rn(v - vh);
}

static __device__ __forceinline__ void split_pack2(float a, float b,
                                                   uint32_t& hi, uint32_t& lo) {
    float ah = __bfloat162float(__float2bfloat16_rn(a));
    float bh2 = __bfloat162float(__float2bfloat16_rn(b));
    __nv_bfloat162 h2 = __floats2bfloat162_rn(ah, bh2);
    __nv_bfloat162 l2 = __floats2bfloat162_rn(a - ah, b - bh2);
    hi = *(uint32_t*)&h2;
    lo = *(uint32_t*)&l2;
}

#define LDSM_X4(r0,r1,r2,r3,addr) \
    asm volatile("ldmatrix.sync.aligned.m8n8.x4.shared.b16 {%0,%1,%2,%3}, [%4];" \
        : "=r"(r0),"=r"(r1),"=r"(r2),"=r"(r3) : "r"(addr))

#define LDSM_X4_T(r0,r1,r2,r3,addr) \
    asm volatile("ldmatrix.sync.aligned.m8n8.x4.trans.shared.b16 {%0,%1,%2,%3}, [%4];" \
        : "=r"(r0),"=r"(r1),"=r"(r2),"=r"(r3) : "r"(addr))

#define MMA_BF16(C, A, b0_, b1_) \
    asm volatile("mma.sync.aligned.m16n8k16.row.col.f32.bf16.bf16.f32 " \
        "{%0,%1,%2,%3}, {%4,%5,%6,%7}, {%8,%9}, {%0,%1,%2,%3};" \
        : "+f"((C)[0]), "+f"((C)[1]), "+f"((C)[2]), "+f"((C)[3]) \
        : "r"((A)[0]), "r"((A)[1]), "r"((A)[2]), "r"((A)[3]), "r"(b0_), "r"(b1_))

#define CP_A16(dst, src) \
    asm volatile("cp.async.cg.shared.global [%0], [%1], 16;" :: "r"(dst), "l"(src))
#define CP_COMMIT() asm volatile("cp.async.commit_group;")
#define CP_WAIT1() asm volatile("cp.async.wait_group 1;")
#define CP_WAIT0() asm volatile("cp.async.wait_group 0;")

// ---------------- LayerNorm + split-bf16 output ------------------------------
template <int DIM>
__global__ void ln_split_kernel(const float* __restrict__ x, const float* __restrict__ g,
                                const float* __restrict__ b,
                                bf16* __restrict__ oh, bf16* __restrict__ ol) {
    constexpr int NW = DIM / 32;
    __shared__ float red[NW];
    int row = blockIdx.x;
    int t = threadIdx.x;
    float v = x[(size_t)row * DIM + t];

    float s = v;
    #pragma unroll
    for (int o = 16; o; o >>= 1) s += __shfl_xor_sync(0xFFFFFFFFu, s, o);
    if ((t & 31) == 0) red[t >> 5] = s;
    __syncthreads();
    float tot = 0.f;
    #pragma unroll
    for (int i = 0; i < NW; i++) tot += red[i];
    float mean = tot / (float)DIM;
    __syncthreads();

    float d = v - mean;
    float s2 = d * d;
    #pragma unroll
    for (int o = 16; o; o >>= 1) s2 += __shfl_xor_sync(0xFFFFFFFFu, s2, o);
    if ((t & 31) == 0) red[t >> 5] = s2;
    __syncthreads();
    float var = 0.f;
    #pragma unroll
    for (int i = 0; i < NW; i++) var += red[i];
    var /= (float)DIM;

    float out = d * rsqrtf(var + 1e-5f) * g[t] + b[t];
    split1(out, oh[(size_t)row * DIM + t], ol[(size_t)row * DIM + t]);
}

// ---------------- merged weight split (one launch) ---------------------------
__global__ void splitw_all_kernel(const float* __restrict__ Wvqk, const float* __restrict__ Wcqk,
                                  const float* __restrict__ Wvv,  const float* __restrict__ Wcv,
                                  const float* __restrict__ Wov,  const float* __restrict__ Woc) {
    int i = blockIdx.x * 256 + threadIdx.x;
    // segment sizes: 131072, 32768, 65536, 16384, 65536, 16384 (total 327680)
    if (i < 131072) { split1(Wvqk[i], g_Wvqk_h[i], g_Wvqk_l[i]); return; }
    i -= 131072;
    if (i < 32768)  { split1(Wcqk[i], g_Wcqk_h[i], g_Wcqk_l[i]); return; }
    i -= 32768;
    if (i < 65536)  { split1(Wvv[i],  g_Wvv_h[i],  g_Wvv_l[i]);  return; }
    i -= 65536;
    if (i < 16384)  { split1(Wcv[i],  g_Wcv_h[i],  g_Wcv_l[i]);  return; }
    i -= 16384;
    if (i < 65536)  { split1(Wov[i],  g_Wov_h[i],  g_Wov_l[i]);  return; }
    i -= 65536;
    if (i < 16384)  { split1(Woc[i],  g_Woc_h[i],  g_Woc_l[i]); }
}

// ---- RMSNorm over 512 + split-bf16 write to head-interleaved Q/K buffers ---
__global__ void rms512_split_kernel(const float* __restrict__ x, const float* __restrict__ s,
                                    bf16* __restrict__ Qh, bf16* __restrict__ Ql,
                                    bf16* __restrict__ Kh, bf16* __restrict__ Kl,
                                    int coff) {
    __shared__ float red[8];
    int row = blockIdx.x;
    int t = threadIdx.x;
    const float* xr = x + (size_t)row * 512;
    float a = xr[t], c = xr[t + 256];
    float ss = a * a + c * c;
    #pragma unroll
    for (int o = 16; o; o >>= 1) ss += __shfl_xor_sync(0xFFFFFFFFu, ss, o);
    if ((t & 31) == 0) red[t >> 5] = ss;
    __syncthreads();
    float tot = 0.f;
    #pragma unroll
    for (int i = 0; i < 8; i++) tot += red[i];
    float r = rsqrtf(tot / 512.f + 1e-6f);

    float qv = a * r * s[t] * 0.125f;
    float kv = c * r * s[t + 256];
    int h = t >> 6, d = t & 63;
    size_t di = (size_t)row * 512 + h * 128 + coff + d;
    split1(qv, Qh[di], Ql[di]);
    split1(kv, Kh[di], Kl[di]);
}

// ---------------- Tensor-core GEMM (split-bf16 x3) ---------------------------
struct GemmSmem {
    bf16 Ah[64][72];
    bf16 Al[64][72];
    bf16 Bh[64][72];
    bf16 Bl[64][72];
};

__global__ void __launch_bounds__(128)
mma_gemm_kernel(const bf16* __restrict__ Ah_, const bf16* __restrict__ Al_,
                const bf16* __restrict__ Bh_, const bf16* __restrict__ Bl_,
                const float* __restrict__ bias, float* __restrict__ C,
                int K, int Nc,
                bf16* __restrict__ oh, bf16* __restrict__ ol, int coff) {
    __shared__ GemmSmem sm;
    int tid = threadIdx.x;
    int lane = tid & 31;
    int wid = tid >> 5;
    int m0 = wid * 16;
    int g = lane >> 2, t4 = lane & 3;
    int bm0 = blockIdx.y * 64;
    int bn0 = blockIdx.x * 64;

    const uint32_t HL = 64 * 72 * 2;
    float cC[8][4] = {};

    for (int k0 = 0; k0 < K; k0 += 64) {
        for (int idx = tid; idx < 512; idx += 128) {
            int tok = idx >> 3;
            int c8 = (idx & 7) << 3;
            size_t abase = (size_t)(bm0 + tok) * K + k0 + c8;
            *(uint4*)&sm.Ah[tok][c8] = *(const uint4*)&Ah_[abase];
            *(uint4*)&sm.Al[tok][c8] = *(const uint4*)&Al_[abase];
            size_t bbase = (size_t)(k0 + tok) * Nc + bn0 + c8;
            *(uint4*)&sm.Bh[tok][c8] = *(const uint4*)&Bh_[bbase];
            *(uint4*)&sm.Bl[tok][c8] = *(const uint4*)&Bl_[bbase];
        }
        __syncthreads();

        #pragma unroll
        for (int j = 0; j < 4; j++) {
            uint32_t ah[4], al[4];
            uint32_t aaddr = smem_u32(&sm.Ah[m0 + (lane & 15)][j * 16 + (lane >> 4) * 8]);
            LDSM_X4(ah[0], ah[1], ah[2], ah[3], aaddr);
            LDSM_X4(al[0], al[1], al[2], al[3], aaddr + HL);
            #pragma unroll
            for (int nh = 0; nh < 4; nh++) {
                uint32_t bh0, bh1, bh2, bh3, bl0, bl1, bl2, bl3;
                uint32_t baddr = smem_u32(&sm.Bh[j * 16 + ((lane >> 3) & 1) * 8 + (lane & 7)]
                                                [nh * 16 + (lane >> 4) * 8]);
                LDSM_X4_T(bh0, bh1, bh2, bh3, baddr);
                LDSM_X4_T(bl0, bl1, bl2, bl3, baddr + HL);
                MMA_BF16(cC[2 * nh], ah, bh0, bh1);
                MMA_BF16(cC[2 * nh], ah, bl0, bl1);
                MMA_BF16(cC[2 * nh], al, bh0, bh1);
                MMA_BF16(cC[2 * nh + 1], ah, bh2, bh3);
                MMA_BF16(cC[2 * nh + 1], ah, bl2, bl3);
                MMA_BF16(cC[2 * nh + 1], al, bh2, bh3);
            }
        }
        __syncthreads();
    }

    int r0 = bm0 + m0 + g;
    if (oh) {
        #pragma unroll
        for (int nf = 0; nf < 8; nf++) {
            int n = bn0 + nf * 8 + t4 * 2;
            float b0 = bias[n], b1 = bias[n + 1];
            size_t di0 = (size_t)r0 * 512 + ((n >> 6) * 128 + coff + (n & 63));
            size_t di1 = (size_t)(r0 + 8) * 512 + ((n >> 6) * 128 + coff + (n & 63));
            uint32_t h0, l0, h1, l1;
            split_pack2(cC[nf][0] + b0, cC[nf][1] + b1, h0, l0);
            split_pack2(cC[nf][2] + b0, cC[nf][3] + b1, h1, l1);
            *(uint32_t*)&oh[di0] = h0; *(uint32_t*)&ol[di0] = l0;
            *(uint32_t*)&oh[di1] = h1; *(uint32_t*)&ol[di1] = l1;
        }
    } else {
        #pragma unroll
        for (int nf = 0; nf < 8; nf++) {
            int n = bn0 + nf * 8 + t4 * 2;
            float b0 = bias[n], b1 = bias[n + 1];
            *(float2*)&C[(size_t)r0 * Nc + n] =
                make_float2(cC[nf][0] + b0, cC[nf][1] + b1);
            *(float2*)&C[(size_t)(r0 + 8) * Nc + n] =
                make_float2(cC[nf][2] + b0, cC[nf][3] + b1);
        }
    }
}

// ---------------- Tensor-core attention (FA2 + cp.async pipeline) -----------
// TQ=128, 8 warps x 16 rows. 2-stage cp.async double buffer for K/V.
struct AttnSmem {
    bf16 Qh[128][136];     // 34816 B
    bf16 Ql[128][136];
    bf16 Kh[2][64][136];   // 2 x 17408 B
    bf16 Kl[2][64][136];
    bf16 Vh[2][64][136];
    bf16 Vl[2][64][136];
};  // 208,896 B -> 1 CTA/SM

__global__ void __launch_bounds__(256, 1)
attn_kernel(const bf16* __restrict__ gQh, const bf16* __restrict__ gQl,
            const bf16* __restrict__ gKh, const bf16* __restrict__ gKl,
            const bf16* __restrict__ gVh, const bf16* __restrict__ gVl,
            bf16* __restrict__ ovph, bf16* __restrict__ ovpl,
            bf16* __restrict__ ocph, bf16* __restrict__ ocpl) {
    extern __shared__ char smraw[];
    AttnSmem& sm = *(AttnSmem*)smraw;
    int tid = threadIdx.x;
    int lane = tid & 31;
    int wid = tid >> 5;       // 0..7
    int m0 = wid * 16;
    int g = lane >> 2, t4 = lane & 3;

    int bh_ = blockIdx.y;
    int b = bh_ >> 2;
    int h = bh_ & 3;
    int n0q = blockIdx.x * 128;

    const uint32_t QHL = 128 * 136 * 2;      // Qh -> Ql
    const uint32_t KVHL = 2 * 64 * 136 * 2;  // Kh[st] -> Kl[st], Vh[st] -> Vl[st]

    // ---- Fill Q tile (hi+lo) ----
    for (int idx = tid; idx < 2048; idx += 256) {
        int tok = idx >> 4;
        int c8 = (idx & 15) << 3;
        size_t base = (size_t)(b * NN + n0q + tok) * 512 + h * 128 + c8;
        *(uint4*)&sm.Qh[tok][c8] = *(const uint4*)&gQh[base];
        *(uint4*)&sm.Ql[tok][c8] = *(const uint4*)&gQl[base];
    }

    float m_[2] = {-1e30f, -1e30f};
    float l_[2] = {0.f, 0.f};
    float cO[16][4] = {};

    // ---- prologue: prefetch tile 0 into stage 0 ----
    {
        int kn0 = 0;
        for (int idx = tid; idx < 1024; idx += 256) {
            int tok = idx >> 4;
            int c8 = (idx & 15) << 3;
            size_t base = (size_t)(b * NN + kn0 + tok) * 512 + h * 128 + c8;
            CP_A16(smem_u32(&sm.Kh[0][tok][c8]), &gKh[base]);
            CP_A16(smem_u32(&sm.Kl[0][tok][c8]), &gKl[base]);
            CP_A16(smem_u32(&sm.Vh[0][tok][c8]), &gVh[base]);
            CP_A16(smem_u32(&sm.Vl[0][tok][c8]), &gVl[base]);
        }
        CP_COMMIT();
    }

    const int NT = NN / 64;
    for (int jt = 0; jt < NT; jt++) {
        int st = jt & 1;
        // prefetch next tile into other stage (its previous readers done at
        // the trailing __syncthreads of iteration jt-1)
        if (jt + 1 < NT) {
            int kn1 = (jt + 1) * 64;
            int st1 = (jt + 1) & 1;
            for (int idx = tid; idx < 1024; idx += 256) {
                int tok = idx >> 4;
                int c8 = (idx & 15) << 3;
                size_t base = (size_t)(b * NN + kn1 + tok) * 512 + h * 128 + c8;
                CP_A16(smem_u32(&sm.Kh[st1][tok][c8]), &gKh[base]);
                CP_A16(smem_u32(&sm.Kl[st1][tok][c8]), &gKl[base]);
                CP_A16(smem_u32(&sm.Vh[st1][tok][c8]), &gVh[base]);
                CP_A16(smem_u32(&sm.Vl[st1][tok][c8]), &gVl[base]);
            }
            CP_COMMIT();
            CP_WAIT1();   // group for tile jt complete; jt+1 may be in flight
        } else {
            CP_WAIT0();
        }
        __syncthreads();

        // ---- S = Q @ K^T (m16 x n64 per warp) ----
        float cS[8][4] = {};
        #pragma unroll
        for (int kf = 0; kf < 8; kf++) {
            int k0 = kf * 16;
            uint32_t ah[4], al[4];
            uint32_t aaddr = smem_u32(&sm.Qh[m0 + (lane & 15)][k0 + (lane >> 4) * 8]);
            LDSM_X4(ah[0], ah[1], ah[2], ah[3], aaddr);
            LDSM_X4(al[0], al[1], al[2], al[3], aaddr + QHL);
            #pragma unroll
            for (int nb = 0; nb < 4; nb++) {
                uint32_t bh0, bh1, bh2, bh3, bl0, bl1, bl2, bl3;
                uint32_t baddr = smem_u32(&sm.Kh[st][nb * 16 + ((lane >> 4) & 1) * 8 + (lane & 7)]
                                                [k0 + ((lane >> 3) & 1) * 8]);
                LDSM_X4(bh0, bh1, bh2, bh3, baddr);
                LDSM_X4(bl0, bl1, bl2, bl3, baddr + KVHL);
                MMA_BF16(cS[2 * nb], ah, bh0, bh1);
                MMA_BF16(cS[2 * nb], ah, bl0, bl1);
                MMA_BF16(cS[2 * nb], al, bh0, bh1);
                MMA_BF16(cS[2 * nb + 1], ah, bh2, bh3);
                MMA_BF16(cS[2 * nb + 1], ah, bl2, bl3);
                MMA_BF16(cS[2 * nb + 1], al, bh2, bh3);
            }
        }

        // ---- Register softmax ----
        #pragma unroll
        for (int r = 0; r < 2; r++) {
            float mx = -1e30f;
            #pragma unroll
            for (int n = 0; n < 8; n++)
                mx = fmaxf(mx, fmaxf(cS[n][2 * r], cS[n][2 * r + 1]));
            mx = fmaxf(mx, __shfl_xor_sync(0xFFFFFFFFu, mx, 1));
            mx = fmaxf(mx, __shfl_xor_sync(0xFFFFFFFFu, mx, 2));
            float m_new = fmaxf(m_[r], mx);
            float alpha = __expf(m_[r] - m_new);
            float sum = 0.f;
            #pragma unroll
            for (int n = 0; n < 8; n++) {
                float p0 = __expf(cS[n][2 * r]     - m_new);
                float p1 = __expf(cS[n][2 * r + 1] - m_new);
                cS[n][2 * r] = p0; cS[n][2 * r + 1] = p1;
                sum += p0 + p1;
            }
            sum += __shfl_xor_sync(0xFFFFFFFFu, sum, 1);
            sum += __shfl_xor_sync(0xFFFFFFFFu, sum, 2);
            l_[r] = l_[r] * alpha + sum;
            m_[r] = m_new;
            #pragma unroll
            for (int nf = 0; nf < 16; nf++) {
                cO[nf][2 * r]     *= alpha;
                cO[nf][2 * r + 1] *= alpha;
            }
        }

        // ---- Pack P fragments ----
        uint32_t PhA[4][4], PlA[4][4];
        #pragma unroll
        for (int j = 0; j < 4; j++) {
            split_pack2(cS[2 * j][0],     cS[2 * j][1],     PhA[j][0], PlA[j][0]);
            split_pack2(cS[2 * j][2],     cS[2 * j][3],     PhA[j][1], PlA[j][1]);
            split_pack2(cS[2 * j + 1][0], cS[2 * j + 1][1], PhA[j][2], PlA[j][2]);
            split_pack2(cS[2 * j + 1][2], cS[2 * j + 1][3], PhA[j][3], PlA[j][3]);
        }

        // ---- O += P @ V ----
        #pragma unroll
        for (int j = 0; j < 4; j++) {
            #pragma unroll
            for (int nh = 0; nh < 8; nh++) {
                uint32_t bh0, bh1, bh2, bh3, bl0, bl1, bl2, bl3;
                uint32_t baddr = smem_u32(&sm.Vh[st][j * 16 + ((lane >> 3) & 1) * 8 + (lane & 7)]
                                                [nh * 16 + (lane >> 4) * 8]);
                LDSM_X4_T(bh0, bh1, bh2, bh3, baddr);
                LDSM_X4_T(bl0, bl1, bl2, bl3, baddr + KVHL);
                MMA_BF16(cO[2 * nh], PhA[j], bh0, bh1);
                MMA_BF16(cO[2 * nh], PhA[j], bl0, bl1);
                MMA_BF16(cO[2 * nh], PlA[j], bh0, bh1);
                MMA_BF16(cO[2 * nh + 1], PhA[j], bh2, bh3);
                MMA_BF16(cO[2 * nh + 1], PhA[j], bl2, bl3);
                MMA_BF16(cO[2 * nh + 1], PlA[j], bh2, bh3);
            }
        }
        __syncthreads();   // stage st free for prefetch of jt+2
    }

    // ---- Epilogue: normalize, split-bf16 write ----
    float li0 = 1.f / l_[0];
    float li1 = 1.f / l_[1];
    size_t row0 = (size_t)(b * NN + n0q + m0 + g);
    size_t row1 = row0 + 8;
    #pragma unroll
    for (int nf = 0; nf < 16; nf++) {
        int c = nf * 8 + t4 * 2;
        uint32_t h0, l0, h1, l1;
        split_pack2(cO[nf][0] * li0, cO[nf][1] * li0, h0, l0);
        split_pack2(cO[nf][2] * li1, cO[nf][3] * li1, h1, l1);
        if (c < 64) {
            size_t d0 = row0 * 256 + h * 64 + c, d1 = row1 * 256 + h * 64 + c;
            *(uint32_t*)&ovph[d0] = h0; *(uint32_t*)&ovpl[d0] = l0;
            *(uint32_t*)&ovph[d1] = h1; *(uint32_t*)&ovpl[d1] = l1;
        } else {
            size_t d0 = row0 * 256 + h * 64 + (c - 64), d1 = row1 * 256 + h * 64 + (c - 64);
            *(uint32_t*)&ocph[d0] = h0; *(uint32_t*)&ocpl[d0] = l0;
            *(uint32_t*)&ocph[d1] = h1; *(uint32_t*)&ocpl[d1] = l1;
        }
    }
}

// ---------------- launch ----------------------------------------------------
extern "C" void kernel_launch(void* const* d_in, const int* in_sizes, int n_in,
                              void* d_out, int out_size) {
    const float* V     = (const float*)d_in[0];
    const float* C     = (const float*)d_in[1];
    const float* vn_g  = (const float*)d_in[2];
    const float* vn_b  = (const float*)d_in[3];
    const float* cn_g  = (const float*)d_in[4];
    const float* cn_b  = (const float*)d_in[5];
    const float* W_vqk = (const float*)d_in[6];
    const float* b_vqk = (const float*)d_in[7];
    const float* rms_v = (const float*)d_in[8];
    const float* W_cqk = (const float*)d_in[9];
    const float* b_cqk = (const float*)d_in[10];
    const float* rms_c = (const float*)d_in[11];
    const float* W_vv  = (const float*)d_in[12];
    const float* b_vv  = (const float*)d_in[13];
    const float* W_cv  = (const float*)d_in[14];
    const float* b_cv  = (const float*)d_in[15];
    const float* W_ov  = (const float*)d_in[16];
    const float* b_ov  = (const float*)d_in[17];
    const float* W_oc  = (const float*)d_in[18];
    const float* b_oc  = (const float*)d_in[19];

    float* out_v = (float*)d_out;
    float* out_c = out_v + (size_t)ROWS * VD;

    float *pqkv, *pqkc;
    bf16 *pVnh, *pVnl, *pCnh, *pCnl;
    bf16 *pQh, *pQl, *pKh, *pKl, *pVh, *pVl;
    bf16 *povph, *povpl, *pocph, *pocpl;
    bf16 *wvqkh, *wvqkl, *wcqkh, *wcqkl, *wvvh, *wvvl, *wcvh, *wcvl, *wovh, *wovl, *woch, *wocl;
    cudaGetSymbolAddress((void**)&pqkv, g_qkv);
    cudaGetSymbolAddress((void**)&pqkc, g_qkc);
    cudaGetSymbolAddress((void**)&pVnh, g_Vnh);
    cudaGetSymbolAddress((void**)&pVnl, g_Vnl);
    cudaGetSymbolAddress((void**)&pCnh, g_Cnh);
    cudaGetSymbolAddress((void**)&pCnl, g_Cnl);
    cudaGetSymbolAddress((void**)&pQh, g_Qh);
    cudaGetSymbolAddress((void**)&pQl, g_Ql);
    cudaGetSymbolAddress((void**)&pKh, g_Kh);
    cudaGetSymbolAddress((void**)&pKl, g_Kl);
    cudaGetSymbolAddress((void**)&pVh, g_Vh);
    cudaGetSymbolAddress((void**)&pVl, g_Vl);
    cudaGetSymbolAddress((void**)&povph, g_ovph);
    cudaGetSymbolAddress((void**)&povpl, g_ovpl);
    cudaGetSymbolAddress((void**)&pocph, g_ocph);
    cudaGetSymbolAddress((void**)&pocpl, g_ocpl);
    cudaGetSymbolAddress((void**)&wvqkh, g_Wvqk_h);
    cudaGetSymbolAddress((void**)&wvqkl, g_Wvqk_l);
    cudaGetSymbolAddress((void**)&wcqkh, g_Wcqk_h);
    cudaGetSymbolAddress((void**)&wcqkl, g_Wcqk_l);
    cudaGetSymbolAddress((void**)&wvvh, g_Wvv_h);
    cudaGetSymbolAddress((void**)&wvvl, g_Wvv_l);
    cudaGetSymbolAddress((void**)&wcvh, g_Wcv_h);
    cudaGetSymbolAddress((void**)&wcvl, g_Wcv_l);
    cudaGetSymbolAddress((void**)&wovh, g_Wov_h);
    cudaGetSymbolAddress((void**)&wovl, g_Wov_l);
    cudaGetSymbolAddress((void**)&woch, g_Woc_h);
    cudaGetSymbolAddress((void**)&wocl, g_Woc_l);

    // 1. LayerNorms + one merged weight split
    ln_split_kernel<VD><<<ROWS, VD>>>(V, vn_g, vn_b, pVnh, pVnl);
    ln_split_kernel<CD><<<ROWS, CD>>>(C, cn_g, cn_b, pCnh, pCnl);
    splitw_all_kernel<<<(327680 + 255) / 256, 256>>>(W_vqk, W_cqk, W_vv, W_cv, W_ov, W_oc);

    // 2. Projections (tensor-core split GEMM)
    mma_gemm_kernel<<<dim3(512 / 64, ROWS / 64), 128>>>(pVnh, pVnl, wvqkh, wvqkl, b_vqk, pqkv,
                                                        VD, 512, nullptr, nullptr, 0);
    mma_gemm_kernel<<<dim3(512 / 64, ROWS / 64), 128>>>(pCnh, pCnl, wcqkh, wcqkl, b_cqk, pqkc,
                                                        CD, 512, nullptr, nullptr, 0);
    mma_gemm_kernel<<<dim3(256 / 64, ROWS / 64), 128>>>(pVnh, pVnl, wvvh, wvvl, b_vv, nullptr,
                                                        VD, 256, pVh, pVl, 0);
    mma_gemm_kernel<<<dim3(256 / 64, ROWS / 64), 128>>>(pCnh, pCnl, wcvh, wcvl, b_cv, nullptr,
                                                        CD, 256, pVh, pVl, 64);

    // 3. RMS norms + split-bf16 Q/K writes
    rms512_split_kernel<<<ROWS, 256>>>(pqkv, rms_v, pQh, pQl, pKh, pKl, 0);
    rms512_split_kernel<<<ROWS, 256>>>(pqkc, rms_c, pQh, pQl, pKh, pKl, 64);

    // 4. Attention (TQ=128, cp.async double-buffered)
    cudaFuncSetAttribute(attn_kernel, cudaFuncAttributeMaxDynamicSharedMemorySize,
                         (int)sizeof(AttnSmem));
    attn_kernel<<<dim3(NN / 128, BB * HH), 256, sizeof(AttnSmem)>>>(pQh, pQl, pKh, pKl, pVh, pVl,
                                                                    povph, povpl, pocph, pocpl);

    // 5. Output projections
    mma_gemm_kernel<<<dim3(256 / 64, ROWS / 64), 128>>>(povph, povpl, wovh, wovl, b_ov, out_v,
                                                        INNER, VD, nullptr, nullptr, 0);
    mma_gemm_kernel<<<dim3(64 / 64, ROWS / 64), 128>>>(pocph, pocpl, woch, wocl, b_oc, out_c,
                                                       INNER, CD, nullptr, nullptr, 0);
}

// round 11
// speedup vs baseline: 3.0370x; 1.0234x over previous
#include <cuda_runtime.h>
#include <cuda_bf16.h>
#include <math.h>
#include <stdint.h>

// Problem constants
#define BB 4
#define NN 2048
#define VD 256
#define CD 64
#define HH 4
#define DD 64
#define INNER 256
#define ROWS (BB * NN)   // 8192

typedef __nv_bfloat16 bf16;

// ---------------- scratch (device globals; no allocation allowed) ----------
__device__ float g_qkv[ROWS * 2 * INNER];
__device__ float g_qkc[ROWS * 2 * INNER];

__device__ bf16 g_Vnh[ROWS * VD];
__device__ bf16 g_Vnl[ROWS * VD];
__device__ bf16 g_Cnh[ROWS * CD];
__device__ bf16 g_Cnl[ROWS * CD];
__device__ bf16 g_ovph[ROWS * INNER];
__device__ bf16 g_ovpl[ROWS * INNER];
__device__ bf16 g_ocph[ROWS * INNER];
__device__ bf16 g_ocpl[ROWS * INNER];

__device__ bf16 g_Wvqk_h[VD * 512];
__device__ bf16 g_Wvqk_l[VD * 512];
__device__ bf16 g_Wcqk_h[CD * 512];
__device__ bf16 g_Wcqk_l[CD * 512];
__device__ bf16 g_Wvv_h[VD * INNER];
__device__ bf16 g_Wvv_l[VD * INNER];
__device__ bf16 g_Wcv_h[CD * INNER];
__device__ bf16 g_Wcv_l[CD * INNER];
__device__ bf16 g_Wov_h[INNER * VD];
__device__ bf16 g_Wov_l[INNER * VD];
__device__ bf16 g_Woc_h[INNER * CD];
__device__ bf16 g_Woc_l[INNER * CD];

__device__ bf16 g_Qh[ROWS * 512];
__device__ bf16 g_Ql[ROWS * 512];
__device__ bf16 g_Kh[ROWS * 512];
__device__ bf16 g_Kl[ROWS * 512];
__device__ bf16 g_Vh[ROWS * 512];
__device__ bf16 g_Vl[ROWS * 512];

// ---------------- helpers ---------------------------------------------------
static __device__ __forceinline__ uint32_t smem_u32(const void* p) {
    return (uint32_t)__cvta_generic_to_shared(p);
}

static __device__ __forceinline__ void split1(float v, bf16& h, bf16& l) {
    float vh = __bfloat162float(__float2bfloat16_rn(v));
    h = __float2bfloat16_rn(vh);
    l = __float2bfloat16_rn(v - vh);
}

static __device__ __forceinline__ void split_pack2(float a, float b,
                                                   uint32_t& hi, uint32_t& lo) {
    float ah = __bfloat162float(__float2bfloat16_rn(a));
    float bh2 = __bfloat162float(__float2bfloat16_rn(b));
    __nv_bfloat162 h2 = __floats2bfloat162_rn(ah, bh2);
    __nv_bfloat162 l2 = __floats2bfloat162_rn(a - ah, b - bh2);
    hi = *(uint32_t*)&h2;
    lo = *(uint32_t*)&l2;
}

#define LDSM_X4(r0,r1,r2,r3,addr) \
    asm volatile("ldmatrix.sync.aligned.m8n8.x4.shared.b16 {%0,%1,%2,%3}, [%4];" \
        : "=r"(r0),"=r"(r1),"=r"(r2),"=r"(r3) : "r"(addr))

#define LDSM_X4_T(r0,r1,r2,r3,addr) \
    asm volatile("ldmatrix.sync.aligned.m8n8.x4.trans.shared.b16 {%0,%1,%2,%3}, [%4];" \
        : "=r"(r0),"=r"(r1),"=r"(r2),"=r"(r3) : "r"(addr))

#define MMA_BF16(C, A, b0_, b1_) \
    asm volatile("mma.sync.aligned.m16n8k16.row.col.f32.bf16.bf16.f32 " \
        "{%0,%1,%2,%3}, {%4,%5,%6,%7}, {%8,%9}, {%0,%1,%2,%3};" \
        : "+f"((C)[0]), "+f"((C)[1]), "+f"((C)[2]), "+f"((C)[3]) \
        : "r"((A)[0]), "r"((A)[1]), "r"((A)[2]), "r"((A)[3]), "r"(b0_), "r"(b1_))

#define CP_A16(dst, src) \
    asm volatile("cp.async.cg.shared.global [%0], [%1], 16;" :: "r"(dst), "l"(src))
#define CP_COMMIT() asm volatile("cp.async.commit_group;")
#define CP_WAIT1() asm volatile("cp.async.wait_group 1;")
#define CP_WAIT0() asm volatile("cp.async.wait_group 0;")

// ---------------- LayerNorm + split-bf16 output ------------------------------
template <int DIM>
__global__ void ln_split_kernel(const float* __restrict__ x, const float* __restrict__ g,
                                const float* __restrict__ b,
                                bf16* __restrict__ oh, bf16* __restrict__ ol) {
    constexpr int NW = DIM / 32;
    __shared__ float red[NW];
    int row = blockIdx.x;
    int t = threadIdx.x;
    float v = x[(size_t)row * DIM + t];

    float s = v;
    #pragma unroll
    for (int o = 16; o; o >>= 1) s += __shfl_xor_sync(0xFFFFFFFFu, s, o);
    if ((t & 31) == 0) red[t >> 5] = s;
    __syncthreads();
    float tot = 0.f;
    #pragma unroll
    for (int i = 0; i < NW; i++) tot += red[i];
    float mean = tot / (float)DIM;
    __syncthreads();

    float d = v - mean;
    float s2 = d * d;
    #pragma unroll
    for (int o = 16; o; o >>= 1) s2 += __shfl_xor_sync(0xFFFFFFFFu, s2, o);
    if ((t & 31) == 0) red[t >> 5] = s2;
    __syncthreads();
    float var = 0.f;
    #pragma unroll
    for (int i = 0; i < NW; i++) var += red[i];
    var /= (float)DIM;

    float out = d * rsqrtf(var + 1e-5f) * g[t] + b[t];
    split1(out, oh[(size_t)row * DIM + t], ol[(size_t)row * DIM + t]);
}

// ---------------- merged weight split (one launch) ---------------------------
__global__ void splitw_all_kernel(const float* __restrict__ Wvqk, const float* __restrict__ Wcqk,
                                  const float* __restrict__ Wvv,  const float* __restrict__ Wcv,
                                  const float* __restrict__ Wov,  const float* __restrict__ Woc) {
    int i = blockIdx.x * 256 + threadIdx.x;
    if (i < 131072) { split1(Wvqk[i], g_Wvqk_h[i], g_Wvqk_l[i]); return; }
    i -= 131072;
    if (i < 32768)  { split1(Wcqk[i], g_Wcqk_h[i], g_Wcqk_l[i]); return; }
    i -= 32768;
    if (i < 65536)  { split1(Wvv[i],  g_Wvv_h[i],  g_Wvv_l[i]);  return; }
    i -= 65536;
    if (i < 16384)  { split1(Wcv[i],  g_Wcv_h[i],  g_Wcv_l[i]);  return; }
    i -= 16384;
    if (i < 65536)  { split1(Wov[i],  g_Wov_h[i],  g_Wov_l[i]);  return; }
    i -= 65536;
    if (i < 16384)  { split1(Woc[i],  g_Woc_h[i],  g_Woc_l[i]); }
}

// ---- RMSNorm over 512 + split-bf16 write to head-interleaved Q/K buffers ---
__global__ void rms512_split_kernel(const float* __restrict__ x, const float* __restrict__ s,
                                    bf16* __restrict__ Qh, bf16* __restrict__ Ql,
                                    bf16* __restrict__ Kh, bf16* __restrict__ Kl,
                                    int coff) {
    __shared__ float red[8];
    int row = blockIdx.x;
    int t = threadIdx.x;
    const float* xr = x + (size_t)row * 512;
    float a = xr[t], c = xr[t + 256];
    float ss = a * a + c * c;
    #pragma unroll
    for (int o = 16; o; o >>= 1) ss += __shfl_xor_sync(0xFFFFFFFFu, ss, o);
    if ((t & 31) == 0) red[t >> 5] = ss;
    __syncthreads();
    float tot = 0.f;
    #pragma unroll
    for (int i = 0; i < 8; i++) tot += red[i];
    float r = rsqrtf(tot / 512.f + 1e-6f);

    float qv = a * r * s[t] * 0.125f;
    float kv = c * r * s[t + 256];
    int h = t >> 6, d = t & 63;
    size_t di = (size_t)row * 512 + h * 128 + coff + d;
    split1(qv, Qh[di], Ql[di]);
    split1(kv, Kh[di], Kl[di]);
}

// ---------------- Tensor-core GEMM (split-bf16 x3, pipelined) ----------------
// BM=128, BN=64, BK=64. 256 threads = 8 warps, each m16 x n64.
// 2-stage cp.async; term-major MMA ordering (4 indep accumulator chains).
struct GemmSmem {
    bf16 Ah[2][128][72];   // 36864 B
    bf16 Al[2][128][72];
    bf16 Bh[2][64][72];    // 18432 B
    bf16 Bl[2][64][72];
};  // 110,592 B

__global__ void __launch_bounds__(256)
mma_gemm_kernel(const bf16* __restrict__ Ah_, const bf16* __restrict__ Al_,
                const bf16* __restrict__ Bh_, const bf16* __restrict__ Bl_,
                const float* __restrict__ bias, float* __restrict__ C,
                int K, int Nc,
                bf16* __restrict__ oh, bf16* __restrict__ ol, int coff) {
    extern __shared__ char smraw[];
    GemmSmem& sm = *(GemmSmem*)smraw;
    int tid = threadIdx.x;
    int lane = tid & 31;
    int wid = tid >> 5;
    int m0 = wid * 16;
    int g = lane >> 2, t4 = lane & 3;
    int bm0 = blockIdx.y * 128;
    int bn0 = blockIdx.x * 64;

    const uint32_t AHL = 2 * 128 * 72 * 2;   // Ah[st] -> Al[st]
    const uint32_t BHL = 2 * 64 * 72 * 2;    // Bh[st] -> Bl[st]
    float cC[8][4] = {};

    // prologue: prefetch k-step 0 into stage 0
    {
        for (int idx = tid; idx < 1024; idx += 256) {     // A: 128 x 64 (8/chunk)
            int tok = idx >> 3;
            int c8 = (idx & 7) << 3;
            size_t abase = (size_t)(bm0 + tok) * K + c8;
            CP_A16(smem_u32(&sm.Ah[0][tok][c8]), &Ah_[abase]);
            CP_A16(smem_u32(&sm.Al[0][tok][c8]), &Al_[abase]);
        }
        for (int idx = tid; idx < 512; idx += 256) {      // B: 64 x 64
            int tok = idx >> 3;
            int c8 = (idx & 7) << 3;
            size_t bbase = (size_t)tok * Nc + bn0 + c8;
            CP_A16(smem_u32(&sm.Bh[0][tok][c8]), &Bh_[bbase]);
            CP_A16(smem_u32(&sm.Bl[0][tok][c8]), &Bl_[bbase]);
        }
        CP_COMMIT();
    }

    int NKS = K >> 6;
    for (int ks = 0; ks < NKS; ks++) {
        int st = ks & 1;
        if (ks + 1 < NKS) {
            int st1 = (ks + 1) & 1;
            int k1 = (ks + 1) * 64;
            for (int idx = tid; idx < 1024; idx += 256) {
                int tok = idx >> 3;
                int c8 = (idx & 7) << 3;
                size_t abase = (size_t)(bm0 + tok) * K + k1 + c8;
                CP_A16(smem_u32(&sm.Ah[st1][tok][c8]), &Ah_[abase]);
                CP_A16(smem_u32(&sm.Al[st1][tok][c8]), &Al_[abase]);
            }
            for (int idx = tid; idx < 512; idx += 256) {
                int tok = idx >> 3;
                int c8 = (idx & 7) << 3;
                size_t bbase = (size_t)(k1 + tok) * Nc + bn0 + c8;
                CP_A16(smem_u32(&sm.Bh[st1][tok][c8]), &Bh_[bbase]);
                CP_A16(smem_u32(&sm.Bl[st1][tok][c8]), &Bl_[bbase]);
            }
            CP_COMMIT();
            CP_WAIT1();
        } else {
            CP_WAIT0();
        }
        __syncthreads();

        #pragma unroll
        for (int j = 0; j < 4; j++) {             // k-frags within BK=64
            uint32_t ah[4], al[4];
            uint32_t aaddr = smem_u32(&sm.Ah[st][m0 + (lane & 15)][j * 16 + (lane >> 4) * 8]);
            LDSM_X4(ah[0], ah[1], ah[2], ah[3], aaddr);
            LDSM_X4(al[0], al[1], al[2], al[3], aaddr + AHL);
            #pragma unroll
            for (int p = 0; p < 2; p++) {         // n32 pairs -> 4 accum frags
                uint32_t bh2[2][4], bl2[2][4];
                #pragma unroll
                for (int q = 0; q < 2; q++) {
                    int nh = 2 * p + q;
                    uint32_t baddr = smem_u32(&sm.Bh[st][j * 16 + ((lane >> 3) & 1) * 8 + (lane & 7)]
                                                    [nh * 16 + (lane >> 4) * 8]);
                    LDSM_X4_T(bh2[q][0], bh2[q][1], bh2[q][2], bh2[q][3], baddr);
                    LDSM_X4_T(bl2[q][0], bl2[q][1], bl2[q][2], bl2[q][3], baddr + BHL);
                }
                float* c0 = cC[4 * p + 0]; float* c1 = cC[4 * p + 1];
                float* c2 = cC[4 * p + 2]; float* c3 = cC[4 * p + 3];
                // term hh (4 independent)
                MMA_BF16(c0, ah, bh2[0][0], bh2[0][1]);
                MMA_BF16(c1, ah, bh2[0][2], bh2[0][3]);
                MMA_BF16(c2, ah, bh2[1][0], bh2[1][1]);
                MMA_BF16(c3, ah, bh2[1][2], bh2[1][3]);
                // term h*l
                MMA_BF16(c0, ah, bl2[0][0], bl2[0][1]);
                MMA_BF16(c1, ah, bl2[0][2], bl2[0][3]);
                MMA_BF16(c2, ah, bl2[1][0], bl2[1][1]);
                MMA_BF16(c3, ah, bl2[1][2], bl2[1][3]);
                // term l*h
                MMA_BF16(c0, al, bh2[0][0], bh2[0][1]);
                MMA_BF16(c1, al, bh2[0][2], bh2[0][3]);
                MMA_BF16(c2, al, bh2[1][0], bh2[1][1]);
                MMA_BF16(c3, al, bh2[1][2], bh2[1][3]);
            }
        }
        __syncthreads();
    }

    int r0 = bm0 + m0 + g;
    if (oh) {
        #pragma unroll
        for (int nf = 0; nf < 8; nf++) {
            int n = bn0 + nf * 8 + t4 * 2;
            float b0 = bias[n], b1 = bias[n + 1];
            size_t di0 = (size_t)r0 * 512 + ((n >> 6) * 128 + coff + (n & 63));
            size_t di1 = (size_t)(r0 + 8) * 512 + ((n >> 6) * 128 + coff + (n & 63));
            uint32_t h0, l0, h1, l1;
            split_pack2(cC[nf][0] + b0, cC[nf][1] + b1, h0, l0);
            split_pack2(cC[nf][2] + b0, cC[nf][3] + b1, h1, l1);
            *(uint32_t*)&oh[di0] = h0; *(uint32_t*)&ol[di0] = l0;
            *(uint32_t*)&oh[di1] = h1; *(uint32_t*)&ol[di1] = l1;
        }
    } else {
        #pragma unroll
        for (int nf = 0; nf < 8; nf++) {
            int n = bn0 + nf * 8 + t4 * 2;
            float b0 = bias[n], b1 = bias[n + 1];
            *(float2*)&C[(size_t)r0 * Nc + n] =
                make_float2(cC[nf][0] + b0, cC[nf][1] + b1);
            *(float2*)&C[(size_t)(r0 + 8) * Nc + n] =
                make_float2(cC[nf][2] + b0, cC[nf][3] + b1);
        }
    }
}

// ---------------- Tensor-core attention (FA2 + cp.async pipeline) -----------
// TQ=128, 8 warps x 16 rows. 2-stage cp.async; term-major MMA ordering.
struct AttnSmem {
    bf16 Qh[128][136];
    bf16 Ql[128][136];
    bf16 Kh[2][64][136];
    bf16 Kl[2][64][136];
    bf16 Vh[2][64][136];
    bf16 Vl[2][64][136];
};  // 208,896 B -> 1 CTA/SM

__global__ void __launch_bounds__(256, 1)
attn_kernel(const bf16* __restrict__ gQh, const bf16* __restrict__ gQl,
            const bf16* __restrict__ gKh, const bf16* __restrict__ gKl,
            const bf16* __restrict__ gVh, const bf16* __restrict__ gVl,
            bf16* __restrict__ ovph, bf16* __restrict__ ovpl,
            bf16* __restrict__ ocph, bf16* __restrict__ ocpl) {
    extern __shared__ char smraw[];
    AttnSmem& sm = *(AttnSmem*)smraw;
    int tid = threadIdx.x;
    int lane = tid & 31;
    int wid = tid >> 5;
    int m0 = wid * 16;
    int g = lane >> 2, t4 = lane & 3;

    int bh_ = blockIdx.y;
    int b = bh_ >> 2;
    int h = bh_ & 3;
    int n0q = blockIdx.x * 128;

    const uint32_t QHL = 128 * 136 * 2;
    const uint32_t KVHL = 2 * 64 * 136 * 2;

    for (int idx = tid; idx < 2048; idx += 256) {
        int tok = idx >> 4;
        int c8 = (idx & 15) << 3;
        size_t base = (size_t)(b * NN + n0q + tok) * 512 + h * 128 + c8;
        *(uint4*)&sm.Qh[tok][c8] = *(const uint4*)&gQh[base];
        *(uint4*)&sm.Ql[tok][c8] = *(const uint4*)&gQl[base];
    }

    float m_[2] = {-1e30f, -1e30f};
    float l_[2] = {0.f, 0.f};
    float cO[16][4] = {};

    {
        for (int idx = tid; idx < 1024; idx += 256) {
            int tok = idx >> 4;
            int c8 = (idx & 15) << 3;
            size_t base = (size_t)(b * NN + tok) * 512 + h * 128 + c8;
            CP_A16(smem_u32(&sm.Kh[0][tok][c8]), &gKh[base]);
            CP_A16(smem_u32(&sm.Kl[0][tok][c8]), &gKl[base]);
            CP_A16(smem_u32(&sm.Vh[0][tok][c8]), &gVh[base]);
            CP_A16(smem_u32(&sm.Vl[0][tok][c8]), &gVl[base]);
        }
        CP_COMMIT();
    }

    const int NT = NN / 64;
    for (int jt = 0; jt < NT; jt++) {
        int st = jt & 1;
        if (jt + 1 < NT) {
            int kn1 = (jt + 1) * 64;
            int st1 = (jt + 1) & 1;
            for (int idx = tid; idx < 1024; idx += 256) {
                int tok = idx >> 4;
                int c8 = (idx & 15) << 3;
                size_t base = (size_t)(b * NN + kn1 + tok) * 512 + h * 128 + c8;
                CP_A16(smem_u32(&sm.Kh[st1][tok][c8]), &gKh[base]);
                CP_A16(smem_u32(&sm.Kl[st1][tok][c8]), &gKl[base]);
                CP_A16(smem_u32(&sm.Vh[st1][tok][c8]), &gVh[base]);
                CP_A16(smem_u32(&sm.Vl[st1][tok][c8]), &gVl[base]);
            }
            CP_COMMIT();
            CP_WAIT1();
        } else {
            CP_WAIT0();
        }
        __syncthreads();

        // ---- S = Q @ K^T : term-major over nb pairs ----
        float cS[8][4] = {};
        #pragma unroll
        for (int kf = 0; kf < 8; kf++) {
            int k0 = kf * 16;
            uint32_t ah[4], al[4];
            uint32_t aaddr = smem_u32(&sm.Qh[m0 + (lane & 15)][k0 + (lane >> 4) * 8]);
            LDSM_X4(ah[0], ah[1], ah[2], ah[3], aaddr);
            LDSM_X4(al[0], al[1], al[2], al[3], aaddr + QHL);
            #pragma unroll
            for (int p = 0; p < 2; p++) {          // nb pairs {0,1},{2,3}
                uint32_t bh2[2][4], bl2[2][4];
                #pragma unroll
                for (int q = 0; q < 2; q++) {
                    int nb = 2 * p + q;
                    uint32_t baddr = smem_u32(&sm.Kh[st][nb * 16 + ((lane >> 4) & 1) * 8 + (lane & 7)]
                                                    [k0 + ((lane >> 3) & 1) * 8]);
                    LDSM_X4(bh2[q][0], bh2[q][1], bh2[q][2], bh2[q][3], baddr);
                    LDSM_X4(bl2[q][0], bl2[q][1], bl2[q][2], bl2[q][3], baddr + KVHL);
                }
                float* c0 = cS[4 * p + 0]; float* c1 = cS[4 * p + 1];
                float* c2 = cS[4 * p + 2]; float* c3 = cS[4 * p + 3];
                MMA_BF16(c0, ah, bh2[0][0], bh2[0][1]);
                MMA_BF16(c1, ah, bh2[0][2], bh2[0][3]);
                MMA_BF16(c2, ah, bh2[1][0], bh2[1][1]);
                MMA_BF16(c3, ah, bh2[1][2], bh2[1][3]);
                MMA_BF16(c0, ah, bl2[0][0], bl2[0][1]);
                MMA_BF16(c1, ah, bl2[0][2], bl2[0][3]);
                MMA_BF16(c2, ah, bl2[1][0], bl2[1][1]);
                MMA_BF16(c3, ah, bl2[1][2], bl2[1][3]);
                MMA_BF16(c0, al, bh2[0][0], bh2[0][1]);
                MMA_BF16(c1, al, bh2[0][2], bh2[0][3]);
                MMA_BF16(c2, al, bh2[1][0], bh2[1][1]);
                MMA_BF16(c3, al, bh2[1][2], bh2[1][3]);
            }
        }

        // ---- Register softmax ----
        #pragma unroll
        for (int r = 0; r < 2; r++) {
            float mx = -1e30f;
            #pragma unroll
            for (int n = 0; n < 8; n++)
                mx = fmaxf(mx, fmaxf(cS[n][2 * r], cS[n][2 * r + 1]));
            mx = fmaxf(mx, __shfl_xor_sync(0xFFFFFFFFu, mx, 1));
            mx = fmaxf(mx, __shfl_xor_sync(0xFFFFFFFFu, mx, 2));
            float m_new = fmaxf(m_[r], mx);
            float alpha = __expf(m_[r] - m_new);
            float sum = 0.f;
            #pragma unroll
            for (int n = 0; n < 8; n++) {
                float p0 = __expf(cS[n][2 * r]     - m_new);
                float p1 = __expf(cS[n][2 * r + 1] - m_new);
                cS[n][2 * r] = p0; cS[n][2 * r + 1] = p1;
                sum += p0 + p1;
            }
            sum += __shfl_xor_sync(0xFFFFFFFFu, sum, 1);
            sum += __shfl_xor_sync(0xFFFFFFFFu, sum, 2);
            l_[r] = l_[r] * alpha + sum;
            m_[r] = m_new;
            #pragma unroll
            for (int nf = 0; nf < 16; nf++) {
                cO[nf][2 * r]     *= alpha;
                cO[nf][2 * r + 1] *= alpha;
            }
        }

        // ---- Pack P fragments ----
        uint32_t PhA[4][4], PlA[4][4];
        #pragma unroll
        for (int j = 0; j < 4; j++) {
            split_pack2(cS[2 * j][0],     cS[2 * j][1],     PhA[j][0], PlA[j][0]);
            split_pack2(cS[2 * j][2],     cS[2 * j][3],     PhA[j][1], PlA[j][1]);
            split_pack2(cS[2 * j + 1][0], cS[2 * j + 1][1], PhA[j][2], PlA[j][2]);
            split_pack2(cS[2 * j + 1][2], cS[2 * j + 1][3], PhA[j][3], PlA[j][3]);
        }

        // ---- O += P @ V : term-major over nh pairs ----
        #pragma unroll
        for (int j = 0; j < 4; j++) {
            #pragma unroll
            for (int p = 0; p < 4; p++) {          // nh pairs
                uint32_t bh2[2][4], bl2[2][4];
                #pragma unroll
                for (int q = 0; q < 2; q++) {
                    int nh = 2 * p + q;
                    uint32_t baddr = smem_u32(&sm.Vh[st][j * 16 + ((lane >> 3) & 1) * 8 + (lane & 7)]
                                                    [nh * 16 + (lane >> 4) * 8]);
                    LDSM_X4_T(bh2[q][0], bh2[q][1], bh2[q][2], bh2[q][3], baddr);
                    LDSM_X4_T(bl2[q][0], bl2[q][1], bl2[q][2], bl2[q][3], baddr + KVHL);
                }
                float* c0 = cO[4 * p + 0]; float* c1 = cO[4 * p + 1];
                float* c2 = cO[4 * p + 2]; float* c3 = cO[4 * p + 3];
                MMA_BF16(c0, PhA[j], bh2[0][0], bh2[0][1]);
                MMA_BF16(c1, PhA[j], bh2[0][2], bh2[0][3]);
                MMA_BF16(c2, PhA[j], bh2[1][0], bh2[1][1]);
                MMA_BF16(c3, PhA[j], bh2[1][2], bh2[1][3]);
                MMA_BF16(c0, PhA[j], bl2[0][0], bl2[0][1]);
                MMA_BF16(c1, PhA[j], bl2[0][2], bl2[0][3]);
                MMA_BF16(c2, PhA[j], bl2[1][0], bl2[1][1]);
                MMA_BF16(c3, PhA[j], bl2[1][2], bl2[1][3]);
                MMA_BF16(c0, PlA[j], bh2[0][0], bh2[0][1]);
                MMA_BF16(c1, PlA[j], bh2[0][2], bh2[0][3]);
                MMA_BF16(c2, PlA[j], bh2[1][0], bh2[1][1]);
                MMA_BF16(c3, PlA[j], bh2[1][2], bh2[1][3]);
            }
        }
        __syncthreads();
    }

    // ---- Epilogue ----
    float li0 = 1.f / l_[0];
    float li1 = 1.f / l_[1];
    size_t row0 = (size_t)(b * NN + n0q + m0 + g);
    size_t row1 = row0 + 8;
    #pragma unroll
    for (int nf = 0; nf < 16; nf++) {
        int c = nf * 8 + t4 * 2;
        uint32_t h0, l0, h1, l1;
        split_pack2(cO[nf][0] * li0, cO[nf][1] * li0, h0, l0);
        split_pack2(cO[nf][2] * li1, cO[nf][3] * li1, h1, l1);
        if (c < 64) {
            size_t d0 = row0 * 256 + h * 64 + c, d1 = row1 * 256 + h * 64 + c;
            *(uint32_t*)&ovph[d0] = h0; *(uint32_t*)&ovpl[d0] = l0;
            *(uint32_t*)&ovph[d1] = h1; *(uint32_t*)&ovpl[d1] = l1;
        } else {
            size_t d0 = row0 * 256 + h * 64 + (c - 64), d1 = row1 * 256 + h * 64 + (c - 64);
            *(uint32_t*)&ocph[d0] = h0; *(uint32_t*)&ocpl[d0] = l0;
            *(uint32_t*)&ocph[d1] = h1; *(uint32_t*)&ocpl[d1] = l1;
        }
    }
}

// ---------------- launch ----------------------------------------------------
extern "C" void kernel_launch(void* const* d_in, const int* in_sizes, int n_in,
                              void* d_out, int out_size) {
    const float* V     = (const float*)d_in[0];
    const float* C     = (const float*)d_in[1];
    const float* vn_g  = (const float*)d_in[2];
    const float* vn_b  = (const float*)d_in[3];
    const float* cn_g  = (const float*)d_in[4];
    const float* cn_b  = (const float*)d_in[5];
    const float* W_vqk = (const float*)d_in[6];
    const float* b_vqk = (const float*)d_in[7];
    const float* rms_v = (const float*)d_in[8];
    const float* W_cqk = (const float*)d_in[9];
    const float* b_cqk = (const float*)d_in[10];
    const float* rms_c = (const float*)d_in[11];
    const float* W_vv  = (const float*)d_in[12];
    const float* b_vv  = (const float*)d_in[13];
    const float* W_cv  = (const float*)d_in[14];
    const float* b_cv  = (const float*)d_in[15];
    const float* W_ov  = (const float*)d_in[16];
    const float* b_ov  = (const float*)d_in[17];
    const float* W_oc  = (const float*)d_in[18];
    const float* b_oc  = (const float*)d_in[19];

    float* out_v = (float*)d_out;
    float* out_c = out_v + (size_t)ROWS * VD;

    float *pqkv, *pqkc;
    bf16 *pVnh, *pVnl, *pCnh, *pCnl;
    bf16 *pQh, *pQl, *pKh, *pKl, *pVh, *pVl;
    bf16 *povph, *povpl, *pocph, *pocpl;
    bf16 *wvqkh, *wvqkl, *wcqkh, *wcqkl, *wvvh, *wvvl, *wcvh, *wcvl, *wovh, *wovl, *woch, *wocl;
    cudaGetSymbolAddress((void**)&pqkv, g_qkv);
    cudaGetSymbolAddress((void**)&pqkc, g_qkc);
    cudaGetSymbolAddress((void**)&pVnh, g_Vnh);
    cudaGetSymbolAddress((void**)&pVnl, g_Vnl);
    cudaGetSymbolAddress((void**)&pCnh, g_Cnh);
    cudaGetSymbolAddress((void**)&pCnl, g_Cnl);
    cudaGetSymbolAddress((void**)&pQh, g_Qh);
    cudaGetSymbolAddress((void**)&pQl, g_Ql);
    cudaGetSymbolAddress((void**)&pKh, g_Kh);
    cudaGetSymbolAddress((void**)&pKl, g_Kl);
    cudaGetSymbolAddress((void**)&pVh, g_Vh);
    cudaGetSymbolAddress((void**)&pVl, g_Vl);
    cudaGetSymbolAddress((void**)&povph, g_ovph);
    cudaGetSymbolAddress((void**)&povpl, g_ovpl);
    cudaGetSymbolAddress((void**)&pocph, g_ocph);
    cudaGetSymbolAddress((void**)&pocpl, g_ocpl);
    cudaGetSymbolAddress((void**)&wvqkh, g_Wvqk_h);
    cudaGetSymbolAddress((void**)&wvqkl, g_Wvqk_l);
    cudaGetSymbolAddress((void**)&wcqkh, g_Wcqk_h);
    cudaGetSymbolAddress((void**)&wcqkl, g_Wcqk_l);
    cudaGetSymbolAddress((void**)&wvvh, g_Wvv_h);
    cudaGetSymbolAddress((void**)&wvvl, g_Wvv_l);
    cudaGetSymbolAddress((void**)&wcvh, g_Wcv_h);
    cudaGetSymbolAddress((void**)&wcvl, g_Wcv_l);
    cudaGetSymbolAddress((void**)&wovh, g_Wov_h);
    cudaGetSymbolAddress((void**)&wovl, g_Wov_l);
    cudaGetSymbolAddress((void**)&woch, g_Woc_h);
    cudaGetSymbolAddress((void**)&wocl, g_Woc_l);

    // 1. LayerNorms + merged weight split
    ln_split_kernel<VD><<<ROWS, VD>>>(V, vn_g, vn_b, pVnh, pVnl);
    ln_split_kernel<CD><<<ROWS, CD>>>(C, cn_g, cn_b, pCnh, pCnl);
    splitw_all_kernel<<<(327680 + 255) / 256, 256>>>(W_vqk, W_cqk, W_vv, W_cv, W_ov, W_oc);

    // 2. Projections (pipelined tensor-core split GEMM)
    cudaFuncSetAttribute(mma_gemm_kernel, cudaFuncAttributeMaxDynamicSharedMemorySize,
                         (int)sizeof(GemmSmem));
    int gsm = (int)sizeof(GemmSmem);
    mma_gemm_kernel<<<dim3(512 / 64, ROWS / 128), 256, gsm>>>(pVnh, pVnl, wvqkh, wvqkl, b_vqk, pqkv,
                                                              VD, 512, nullptr, nullptr, 0);
    mma_gemm_kernel<<<dim3(512 / 64, ROWS / 128), 256, gsm>>>(pCnh, pCnl, wcqkh, wcqkl, b_cqk, pqkc,
                                                              CD, 512, nullptr, nullptr, 0);
    mma_gemm_kernel<<<dim3(256 / 64, ROWS / 128), 256, gsm>>>(pVnh, pVnl, wvvh, wvvl, b_vv, nullptr,
                                                              VD, 256, pVh, pVl, 0);
    mma_gemm_kernel<<<dim3(256 / 64, ROWS / 128), 256, gsm>>>(pCnh, pCnl, wcvh, wcvl, b_cv, nullptr,
                                                              CD, 256, pVh, pVl, 64);

    // 3. RMS norms + split-bf16 Q/K writes
    rms512_split_kernel<<<ROWS, 256>>>(pqkv, rms_v, pQh, pQl, pKh, pKl, 0);
    rms512_split_kernel<<<ROWS, 256>>>(pqkc, rms_c, pQh, pQl, pKh, pKl, 64);

    // 4. Attention
    cudaFuncSetAttribute(attn_kernel, cudaFuncAttributeMaxDynamicSharedMemorySize,
                         (int)sizeof(AttnSmem));
    attn_kernel<<<dim3(NN / 128, BB * HH), 256, sizeof(AttnSmem)>>>(pQh, pQl, pKh, pKl, pVh, pVl,
                                                                    povph, povpl, pocph, pocpl);

    // 5. Output projections
    mma_gemm_kernel<<<dim3(256 / 64, ROWS / 128), 256, gsm>>>(povph, povpl, wovh, wovl, b_ov, out_v,
                                                              INNER, VD, nullptr, nullptr, 0);
    mma_gemm_kernel<<<dim3(64 / 64, ROWS / 128), 256, gsm>>>(pocph, pocpl, woch, wocl, b_oc, out_c,
                                                             INNER, CD, nullptr, nullptr, 0);
}